// round 1
// baseline (speedup 1.0000x reference)
#include <cuda_runtime.h>
#include <cuda_bf16.h>
#include <math.h>

// Problem constants
constexpr int Bc = 4;
constexpr int Lc = 2048;
constexpr int Dd = 1024;
constexpr int Hh = 16;
constexpr int DK = 64;
constexpr int Mtok = Bc * Lc;   // 8192 token rows

// ---------------- scratch (device globals: allocation-free) ----------------
__device__ float g_Q[Bc * Hh * Lc * DK];   // [B,H,L,DK]
__device__ float g_K[Bc * Hh * Lc * DK];
__device__ float g_V[Bc * Hh * Lc * DK];
__device__ float g_att[Bc * Lc * Dd];      // [B,L,D] attention output

// ---------------- GEMM: C[m,n] = X[m,:] . W[n,:] + bias[n] ----------------
// X: [M, 1024] row-major, W: [1024, 1024] row-major (torch Linear weight)
// mode 0: out[m*1024 + n]
// mode 1: out in [B,H,L,DK]: b=m/L, l=m%L, h=n/64, dk=n%64
constexpr int BM = 64, BN = 64, BK = 16;

__global__ void gemm_bias_kernel(const float* __restrict__ X,
                                 const float* __restrict__ W,
                                 const float* __restrict__ bias,
                                 float* __restrict__ out,
                                 int mode)
{
    __shared__ float Xs[BK][BM + 1];
    __shared__ float Ws[BK][BN + 1];

    const int tid = threadIdx.x;         // 256 threads
    const int tx = tid & 15;
    const int ty = tid >> 4;
    const int m0 = blockIdx.y * BM;
    const int n0 = blockIdx.x * BN;

    float acc[4][4] = {};

    for (int k0 = 0; k0 < Dd; k0 += BK) {
        #pragma unroll
        for (int it = 0; it < 4; it++) {
            int idx = tid + it * 256;     // 0..1023
            int mm  = idx >> 4;           // 0..63
            int kk  = idx & 15;           // 0..15
            Xs[kk][mm] = X[(size_t)(m0 + mm) * Dd + (k0 + kk)];
            Ws[kk][mm] = W[(size_t)(n0 + mm) * Dd + (k0 + kk)];
        }
        __syncthreads();

        #pragma unroll
        for (int k = 0; k < BK; k++) {
            float a[4], b[4];
            #pragma unroll
            for (int i = 0; i < 4; i++) a[i] = Xs[k][ty * 4 + i];
            #pragma unroll
            for (int j = 0; j < 4; j++) b[j] = Ws[k][tx * 4 + j];
            #pragma unroll
            for (int i = 0; i < 4; i++)
                #pragma unroll
                for (int j = 0; j < 4; j++)
                    acc[i][j] += a[i] * b[j];
        }
        __syncthreads();
    }

    #pragma unroll
    for (int i = 0; i < 4; i++) {
        int m = m0 + ty * 4 + i;
        #pragma unroll
        for (int j = 0; j < 4; j++) {
            int n = n0 + tx * 4 + j;
            float v = acc[i][j] + bias[n];
            if (mode == 0) {
                out[(size_t)m * Dd + n] = v;
            } else {
                int b  = m >> 11;      // / 2048
                int l  = m & 2047;
                int h  = n >> 6;
                int dk = n & 63;
                out[(((size_t)(b * Hh + h) * Lc + l) << 6) + dk] = v;
            }
        }
    }
}

// ---------------- causal flash attention ----------------
// grid: (L/64, H, B), 256 threads. Q/K/V in [B,H,L,DK].
// Output att[(b*L + q)*D + h*64 + d]  (ready for O-projection GEMM)
__global__ void attn_kernel(const float* __restrict__ Qg,
                            const float* __restrict__ Kg,
                            const float* __restrict__ Vg,
                            float* __restrict__ att)
{
    extern __shared__ float sm[];
    float* Qs   = sm;                  // 64*65
    float* Ks   = Qs + 64 * 65;
    float* Vs   = Ks + 64 * 65;
    float* Ss   = Vs + 64 * 65;
    float* m_sh = Ss + 64 * 65;        // 64
    float* l_sh = m_sh + 64;           // 64
    float* a_sh = l_sh + 64;           // 64

    const int tid = threadIdx.x;
    const int tx = tid & 15;
    const int ty = tid >> 4;
    const int q0 = blockIdx.x * 64;
    const int h  = blockIdx.y;
    const int b  = blockIdx.z;

    const size_t base = (size_t)(b * Hh + h) * Lc * DK;
    const float* Qbh = Qg + base;
    const float* Kbh = Kg + base;
    const float* Vbh = Vg + base;

    // load Q tile (64 x 64)
    #pragma unroll
    for (int it = 0; it < 16; it++) {
        int idx = tid + it * 256;
        int r = idx >> 6, d = idx & 63;
        Qs[r * 65 + d] = Qbh[(size_t)(q0 + r) * DK + d];
    }
    if (tid < 64) { m_sh[tid] = -3.0e38f; l_sh[tid] = 0.0f; }

    float o[4][4] = {};
    const float scale = 0.125f;   // 1/sqrt(64)
    __syncthreads();

    for (int k0 = 0; k0 <= q0; k0 += 64) {
        // load K, V tiles
        #pragma unroll
        for (int it = 0; it < 16; it++) {
            int idx = tid + it * 256;
            int r = idx >> 6, d = idx & 63;
            Ks[r * 65 + d] = Kbh[(size_t)(k0 + r) * DK + d];
            Vs[r * 65 + d] = Vbh[(size_t)(k0 + r) * DK + d];
        }
        __syncthreads();

        // S = scale * Q K^T  (4x4 microtile per thread), causal mask
        float s[4][4] = {};
        #pragma unroll
        for (int d = 0; d < 64; d++) {
            float a[4], bb[4];
            #pragma unroll
            for (int i = 0; i < 4; i++) a[i]  = Qs[(ty * 4 + i) * 65 + d];
            #pragma unroll
            for (int j = 0; j < 4; j++) bb[j] = Ks[(tx * 4 + j) * 65 + d];
            #pragma unroll
            for (int i = 0; i < 4; i++)
                #pragma unroll
                for (int j = 0; j < 4; j++)
                    s[i][j] += a[i] * bb[j];
        }
        const bool edge = (k0 == q0);
        #pragma unroll
        for (int i = 0; i < 4; i++) {
            int qi = ty * 4 + i;
            #pragma unroll
            for (int j = 0; j < 4; j++) {
                int kj = tx * 4 + j;
                float v = s[i][j] * scale;
                if (edge && (k0 + kj > q0 + qi)) v = -1.0e9f;
                Ss[qi * 65 + kj] = v;
            }
        }
        __syncthreads();

        // online softmax row pass (one thread per query row)
        if (tid < 64) {
            const int r = tid;
            float mold = m_sh[r];
            float mx = mold;
            #pragma unroll 8
            for (int j = 0; j < 64; j++) mx = fmaxf(mx, Ss[r * 65 + j]);
            float alpha = __expf(mold - mx);
            float ps = 0.0f;
            #pragma unroll 8
            for (int j = 0; j < 64; j++) {
                float p = __expf(Ss[r * 65 + j] - mx);
                Ss[r * 65 + j] = p;
                ps += p;
            }
            l_sh[r] = l_sh[r] * alpha + ps;
            m_sh[r] = mx;
            a_sh[r] = alpha;
        }
        __syncthreads();

        // rescale O and accumulate P @ V
        #pragma unroll
        for (int i = 0; i < 4; i++) {
            float al = a_sh[ty * 4 + i];
            #pragma unroll
            for (int j = 0; j < 4; j++) o[i][j] *= al;
        }
        #pragma unroll
        for (int kj = 0; kj < 64; kj++) {
            float p[4], v[4];
            #pragma unroll
            for (int i = 0; i < 4; i++) p[i] = Ss[(ty * 4 + i) * 65 + kj];
            #pragma unroll
            for (int j = 0; j < 4; j++) v[j] = Vs[kj * 65 + tx * 4 + j];
            #pragma unroll
            for (int i = 0; i < 4; i++)
                #pragma unroll
                for (int j = 0; j < 4; j++)
                    o[i][j] += p[i] * v[j];
        }
        __syncthreads();
    }

    // write normalized output to [B,L,D] layout
    #pragma unroll
    for (int i = 0; i < 4; i++) {
        int q = q0 + ty * 4 + i;
        float inv = 1.0f / l_sh[ty * 4 + i];
        #pragma unroll
        for (int j = 0; j < 4; j++) {
            int d = tx * 4 + j;
            att[((size_t)(b * Lc + q)) * Dd + h * DK + d] = o[i][j] * inv;
        }
    }
}

// ---------------- launch ----------------
extern "C" void kernel_launch(void* const* d_in, const int* in_sizes, int n_in,
                              void* d_out, int out_size)
{
    const float* q    = (const float*)d_in[0];
    const float* k    = (const float*)d_in[1];
    const float* v    = (const float*)d_in[2];
    const float* wq_w = (const float*)d_in[3];
    const float* wq_b = (const float*)d_in[4];
    const float* wk_w = (const float*)d_in[5];
    const float* wk_b = (const float*)d_in[6];
    const float* wv_w = (const float*)d_in[7];
    const float* wv_b = (const float*)d_in[8];
    const float* wo_w = (const float*)d_in[9];
    const float* wo_b = (const float*)d_in[10];
    float* out = (float*)d_out;

    float *pQ, *pK, *pV, *pAtt;
    cudaGetSymbolAddress((void**)&pQ,   g_Q);
    cudaGetSymbolAddress((void**)&pK,   g_K);
    cudaGetSymbolAddress((void**)&pV,   g_V);
    cudaGetSymbolAddress((void**)&pAtt, g_att);

    const int attn_smem = (4 * 64 * 65 + 3 * 64) * (int)sizeof(float);  // 67328 B
    cudaFuncSetAttribute(attn_kernel, cudaFuncAttributeMaxDynamicSharedMemorySize, attn_smem);

    dim3 gg(Dd / BN, Mtok / BM);   // (16, 128)

    gemm_bias_kernel<<<gg, 256>>>(q, wq_w, wq_b, pQ, 1);
    gemm_bias_kernel<<<gg, 256>>>(k, wk_w, wk_b, pK, 1);
    gemm_bias_kernel<<<gg, 256>>>(v, wv_w, wv_b, pV, 1);

    dim3 ga(Lc / 64, Hh, Bc);      // (32, 16, 4)
    attn_kernel<<<ga, 256, attn_smem>>>(pQ, pK, pV, pAtt);

    gemm_bias_kernel<<<gg, 256>>>(pAtt, wo_w, wo_b, out, 0);
}

// round 3
// speedup vs baseline: 2.1349x; 2.1349x over previous
#include <cuda_runtime.h>
#include <cuda_bf16.h>
#include <math.h>
#include <cstdint>

// Problem constants
constexpr int Bc = 4;
constexpr int Lc = 2048;
constexpr int Dd = 1024;
constexpr int Hh = 16;
constexpr int DK = 64;
constexpr int Mtok = Bc * Lc;   // 8192

// ---------------- scratch (device globals) ----------------
__device__ float g_Q[Bc * Hh * Lc * DK];   // [B,H,L,DK]
__device__ float g_K[Bc * Hh * Lc * DK];
__device__ float g_V[Bc * Hh * Lc * DK];
__device__ float g_att[Bc * Lc * Dd];      // [B,L,D]

// ---------------- helpers ----------------
__device__ __forceinline__ uint32_t f2tf32(float f) {
    uint32_t r;
    asm("cvt.rna.tf32.f32 %0, %1;" : "=r"(r) : "f"(f));
    return r;
}

__device__ __forceinline__ void mma_tf32(float* d, const uint32_t* a, const uint32_t* b) {
    asm volatile(
        "mma.sync.aligned.m16n8k8.row.col.f32.tf32.tf32.f32 "
        "{%0,%1,%2,%3}, {%4,%5,%6,%7}, {%8,%9}, {%0,%1,%2,%3};\n"
        : "+f"(d[0]), "+f"(d[1]), "+f"(d[2]), "+f"(d[3])
        : "r"(a[0]), "r"(a[1]), "r"(a[2]), "r"(a[3]), "r"(b[0]), "r"(b[1]));
}

__device__ __forceinline__ void st_tf32x4(uint32_t* dst, float4 v) {
    uint4 u;
    u.x = f2tf32(v.x); u.y = f2tf32(v.y); u.z = f2tf32(v.z); u.w = f2tf32(v.w);
    *(uint4*)dst = u;
}

// ===================== tf32 mma GEMM =====================
// C[m,n] = X[m,:] . W[n,:] + bias[n]
// mode 0: out[m*1024+n]; mode 1: out in [B,H,L,DK]
constexpr int GPAD = 20;   // smem row stride (floats) for 16-col tile

__global__ void __launch_bounds__(256) gemm_mma_kernel(const float* __restrict__ X,
                                                       const float* __restrict__ W,
                                                       const float* __restrict__ bias,
                                                       float* __restrict__ out,
                                                       int mode)
{
    __shared__ uint32_t As[2][128 * GPAD];
    __shared__ uint32_t Bs[2][128 * GPAD];

    const int tid  = threadIdx.x;
    const int w    = tid >> 5;
    const int lane = tid & 31;
    const int gid  = lane >> 2;    // 0..7
    const int t4   = lane & 3;     // 0..3

    const int m0 = blockIdx.y * 128;
    const int n0 = blockIdx.x * 128;
    const int mwB = (w >> 2) * 64;   // warp m base (0 or 64)
    const int nwB = (w & 3) * 32;    // warp n base

    // loader mapping: 2 float4 vectors per thread per matrix
    const int lrow0 = (tid >> 2);        // 0..63
    const int lrow1 = lrow0 + 64;        // 64..127
    const int lc4   = (tid & 3) * 4;     // 0,4,8,12

    float acc[4][4][4] = {};

    // preload tile 0
    {
        float4 a0 = *(const float4*)(X + (size_t)(m0 + lrow0) * Dd + lc4);
        float4 a1 = *(const float4*)(X + (size_t)(m0 + lrow1) * Dd + lc4);
        float4 b0 = *(const float4*)(W + (size_t)(n0 + lrow0) * Dd + lc4);
        float4 b1 = *(const float4*)(W + (size_t)(n0 + lrow1) * Dd + lc4);
        st_tf32x4(&As[0][lrow0 * GPAD + lc4], a0);
        st_tf32x4(&As[0][lrow1 * GPAD + lc4], a1);
        st_tf32x4(&Bs[0][lrow0 * GPAD + lc4], b0);
        st_tf32x4(&Bs[0][lrow1 * GPAD + lc4], b1);
    }
    __syncthreads();

    for (int kt = 0; kt < 64; kt++) {
        const int buf = kt & 1;
        float4 pa0, pa1, pb0, pb1;
        if (kt < 63) {
            const int kn = (kt + 1) * 16;
            pa0 = *(const float4*)(X + (size_t)(m0 + lrow0) * Dd + kn + lc4);
            pa1 = *(const float4*)(X + (size_t)(m0 + lrow1) * Dd + kn + lc4);
            pb0 = *(const float4*)(W + (size_t)(n0 + lrow0) * Dd + kn + lc4);
            pb1 = *(const float4*)(W + (size_t)(n0 + lrow1) * Dd + kn + lc4);
        }

        const uint32_t* A = As[buf];
        const uint32_t* B = Bs[buf];
        #pragma unroll
        for (int ks = 0; ks < 2; ks++) {
            const int kk = ks * 8;
            uint32_t af[4][4], bf[4][2];
            #pragma unroll
            for (int tm = 0; tm < 4; tm++) {
                const uint32_t* p = A + (mwB + tm * 16 + gid) * GPAD + kk + t4;
                af[tm][0] = p[0];
                af[tm][1] = p[8 * GPAD];
                af[tm][2] = p[4];
                af[tm][3] = p[8 * GPAD + 4];
            }
            #pragma unroll
            for (int tn = 0; tn < 4; tn++) {
                const uint32_t* p = B + (nwB + tn * 8 + gid) * GPAD + kk + t4;
                bf[tn][0] = p[0];
                bf[tn][1] = p[4];
            }
            #pragma unroll
            for (int tm = 0; tm < 4; tm++)
                #pragma unroll
                for (int tn = 0; tn < 4; tn++)
                    mma_tf32(acc[tm][tn], af[tm], bf[tn]);
        }

        if (kt < 63) {
            const int nb = buf ^ 1;
            st_tf32x4(&As[nb][lrow0 * GPAD + lc4], pa0);
            st_tf32x4(&As[nb][lrow1 * GPAD + lc4], pa1);
            st_tf32x4(&Bs[nb][lrow0 * GPAD + lc4], pb0);
            st_tf32x4(&Bs[nb][lrow1 * GPAD + lc4], pb1);
        }
        __syncthreads();
    }

    // epilogue
    #pragma unroll
    for (int tm = 0; tm < 4; tm++) {
        const int r0 = m0 + mwB + tm * 16 + gid;
        const int r1 = r0 + 8;
        #pragma unroll
        for (int tn = 0; tn < 4; tn++) {
            const int cc = n0 + nwB + tn * 8 + t4 * 2;
            const float bv0 = __ldg(bias + cc);
            const float bv1 = __ldg(bias + cc + 1);
            float2 v0, v1;
            v0.x = acc[tm][tn][0] + bv0;  v0.y = acc[tm][tn][1] + bv1;
            v1.x = acc[tm][tn][2] + bv0;  v1.y = acc[tm][tn][3] + bv1;
            if (mode == 0) {
                *(float2*)(out + (size_t)r0 * Dd + cc) = v0;
                *(float2*)(out + (size_t)r1 * Dd + cc) = v1;
            } else {
                const int h = cc >> 6, dk = cc & 63;
                {
                    const int b = r0 >> 11, l = r0 & 2047;
                    *(float2*)(out + (((size_t)(b * Hh + h) * Lc + l) << 6) + dk) = v0;
                }
                {
                    const int b = r1 >> 11, l = r1 & 2047;
                    *(float2*)(out + (((size_t)(b * Hh + h) * Lc + l) << 6) + dk) = v1;
                }
            }
        }
    }
}

// ===================== tf32 mma causal flash attention =====================
// grid (L/64, H, B), 256 threads (8 warps as 4x2 over the 64x64 tile)
constexpr int QP = 68;   // row stride (elems) for Qs/Ks/Ss
constexpr int VP = 72;   // row stride for Vs
constexpr int ATTN_SMEM_FLOATS = 64 * QP * 3 + 64 * VP + 192;

__global__ void __launch_bounds__(256) attn_mma_kernel(const float* __restrict__ Qg,
                                                       const float* __restrict__ Kg,
                                                       const float* __restrict__ Vg,
                                                       float* __restrict__ att)
{
    extern __shared__ char smraw[];
    uint32_t* Qs = (uint32_t*)smraw;          // 64 x QP (tf32)
    uint32_t* Ks = Qs + 64 * QP;              // 64 x QP (tf32)
    uint32_t* Vs = Ks + 64 * QP;              // 64 x VP (tf32)
    float*    Ss = (float*)(Vs + 64 * VP);    // 64 x QP (f32 scores / tf32 P)
    float* m_sh = Ss + 64 * QP;
    float* l_sh = m_sh + 64;
    float* a_sh = l_sh + 64;

    const int tid  = threadIdx.x;
    const int w    = tid >> 5;
    const int lane = tid & 31;
    const int gid  = lane >> 2;
    const int t4   = lane & 3;

    const int q0 = blockIdx.x * 64;
    const int h  = blockIdx.y;
    const int b  = blockIdx.z;

    const int mwB = (w >> 1) * 16;   // warp row base in tile
    const int nwB = (w & 1) * 32;    // warp col base in tile

    const size_t base = (size_t)(b * Hh + h) * Lc * DK;
    const float* Qbh = Qg + base;
    const float* Kbh = Kg + base;
    const float* Vbh = Vg + base;

    // load Q tile (scaled by 1/8, tf32)
    #pragma unroll
    for (int it = 0; it < 4; it++) {
        const int v = tid + it * 256;
        const int r = v >> 4, c4 = (v & 15) * 4;
        float4 qv = *(const float4*)(Qbh + (size_t)(q0 + r) * DK + c4);
        qv.x *= 0.125f; qv.y *= 0.125f; qv.z *= 0.125f; qv.w *= 0.125f;
        st_tf32x4(&Qs[r * QP + c4], qv);
    }
    if (tid < 64) { m_sh[tid] = -3.0e38f; l_sh[tid] = 0.0f; }

    float o[4][4] = {};
    __syncthreads();

    const int ntiles = q0 / 64 + 1;
    for (int t = 0; t < ntiles; t++) {
        const int k0 = t * 64;

        // load K, V tiles
        #pragma unroll
        for (int it = 0; it < 4; it++) {
            const int v = tid + it * 256;
            const int r = v >> 4, c4 = (v & 15) * 4;
            float4 kv = *(const float4*)(Kbh + (size_t)(k0 + r) * DK + c4);
            float4 vv = *(const float4*)(Vbh + (size_t)(k0 + r) * DK + c4);
            st_tf32x4(&Ks[r * QP + c4], kv);
            st_tf32x4(&Vs[r * VP + c4], vv);
        }
        __syncthreads();

        // S = Q' K^T  (warp tile 16x32: 4 n-tiles, 8 k-steps)
        float s[4][4] = {};
        #pragma unroll
        for (int ks = 0; ks < 8; ks++) {
            const int kk = ks * 8;
            uint32_t af[4];
            {
                const uint32_t* p = Qs + (mwB + gid) * QP + kk + t4;
                af[0] = p[0]; af[1] = p[8 * QP]; af[2] = p[4]; af[3] = p[8 * QP + 4];
            }
            #pragma unroll
            for (int tn = 0; tn < 4; tn++) {
                uint32_t bf[2];
                const uint32_t* p = Ks + (nwB + tn * 8 + gid) * QP + kk + t4;
                bf[0] = p[0]; bf[1] = p[4];
                mma_tf32(s[tn], af, bf);
            }
        }
        // store S to smem
        #pragma unroll
        for (int tn = 0; tn < 4; tn++) {
            const int cc = nwB + tn * 8 + t4 * 2;
            Ss[(mwB + gid)     * QP + cc]     = s[tn][0];
            Ss[(mwB + gid)     * QP + cc + 1] = s[tn][1];
            Ss[(mwB + gid + 8) * QP + cc]     = s[tn][2];
            Ss[(mwB + gid + 8) * QP + cc + 1] = s[tn][3];
        }
        __syncthreads();

        // online softmax: 4 threads per row, 16 cols each
        {
            const int row = tid >> 2, qd = tid & 3;
            const int grow = q0 + row;
            const bool edge = (k0 == q0);
            const float mold = m_sh[row];
            float mx = -3.0e38f;
            #pragma unroll
            for (int j = 0; j < 16; j++) {
                const int c = qd * 16 + j;
                const bool ok = !edge || (k0 + c <= grow);
                const float v = Ss[row * QP + c];
                if (ok) mx = fmaxf(mx, v);
            }
            mx = fmaxf(mx, __shfl_xor_sync(0xffffffff, mx, 1));
            mx = fmaxf(mx, __shfl_xor_sync(0xffffffff, mx, 2));
            const float mnew = fmaxf(mold, mx);
            float ps = 0.0f;
            #pragma unroll
            for (int j = 0; j < 16; j++) {
                const int c = qd * 16 + j;
                const bool ok = !edge || (k0 + c <= grow);
                float p = ok ? __expf(Ss[row * QP + c] - mnew) : 0.0f;
                ps += p;
                Ss[row * QP + c] = __uint_as_float(f2tf32(p));
            }
            ps += __shfl_xor_sync(0xffffffff, ps, 1);
            ps += __shfl_xor_sync(0xffffffff, ps, 2);
            if (qd == 0) {
                const float alpha = __expf(mold - mnew);
                l_sh[row] = l_sh[row] * alpha + ps;
                m_sh[row] = mnew;
                a_sh[row] = alpha;
            }
        }
        __syncthreads();

        // rescale O, then O += P V
        {
            const float a0 = a_sh[mwB + gid];
            const float a1 = a_sh[mwB + gid + 8];
            #pragma unroll
            for (int tn = 0; tn < 4; tn++) {
                o[tn][0] *= a0; o[tn][1] *= a0;
                o[tn][2] *= a1; o[tn][3] *= a1;
            }
        }
        const uint32_t* Su = (const uint32_t*)Ss;
        #pragma unroll
        for (int ks = 0; ks < 8; ks++) {
            const int kk = ks * 8;
            uint32_t af[4];
            {
                const uint32_t* p = Su + (mwB + gid) * QP + kk + t4;
                af[0] = p[0]; af[1] = p[8 * QP]; af[2] = p[4]; af[3] = p[8 * QP + 4];
            }
            #pragma unroll
            for (int tn = 0; tn < 4; tn++) {
                uint32_t bf[2];
                const uint32_t* p = Vs + (kk + t4) * VP + nwB + tn * 8 + gid;
                bf[0] = p[0]; bf[1] = p[4 * VP];
                mma_tf32(o[tn], af, bf);
            }
        }
        __syncthreads();
    }

    // write normalized output to [B,L,D]
    {
        const float inv0 = 1.0f / l_sh[mwB + gid];
        const float inv1 = 1.0f / l_sh[mwB + gid + 8];
        const int r0 = q0 + mwB + gid;
        const int r1 = r0 + 8;
        #pragma unroll
        for (int tn = 0; tn < 4; tn++) {
            const int cc = nwB + tn * 8 + t4 * 2;
            float2 v0, v1;
            v0.x = o[tn][0] * inv0; v0.y = o[tn][1] * inv0;
            v1.x = o[tn][2] * inv1; v1.y = o[tn][3] * inv1;
            *(float2*)(att + ((size_t)(b * Lc + r0)) * Dd + h * DK + cc) = v0;
            *(float2*)(att + ((size_t)(b * Lc + r1)) * Dd + h * DK + cc) = v1;
        }
    }
}

// ---------------- launch ----------------
extern "C" void kernel_launch(void* const* d_in, const int* in_sizes, int n_in,
                              void* d_out, int out_size)
{
    const float* q    = (const float*)d_in[0];
    const float* k    = (const float*)d_in[1];
    const float* v    = (const float*)d_in[2];
    const float* wq_w = (const float*)d_in[3];
    const float* wq_b = (const float*)d_in[4];
    const float* wk_w = (const float*)d_in[5];
    const float* wk_b = (const float*)d_in[6];
    const float* wv_w = (const float*)d_in[7];
    const float* wv_b = (const float*)d_in[8];
    const float* wo_w = (const float*)d_in[9];
    const float* wo_b = (const float*)d_in[10];
    float* out = (float*)d_out;

    float *pQ, *pK, *pV, *pAtt;
    cudaGetSymbolAddress((void**)&pQ,   g_Q);
    cudaGetSymbolAddress((void**)&pK,   g_K);
    cudaGetSymbolAddress((void**)&pV,   g_V);
    cudaGetSymbolAddress((void**)&pAtt, g_att);

    const int attn_smem = ATTN_SMEM_FLOATS * (int)sizeof(float);   // ~71.4 KB
    cudaFuncSetAttribute(attn_mma_kernel, cudaFuncAttributeMaxDynamicSharedMemorySize, attn_smem);

    dim3 gg(Dd / 128, Mtok / 128);   // (8, 64)

    gemm_mma_kernel<<<gg, 256>>>(q, wq_w, wq_b, pQ, 1);
    gemm_mma_kernel<<<gg, 256>>>(k, wk_w, wk_b, pK, 1);
    gemm_mma_kernel<<<gg, 256>>>(v, wv_w, wv_b, pV, 1);

    dim3 ga(Lc / 64, Hh, Bc);        // (32, 16, 4)
    attn_mma_kernel<<<ga, 256, attn_smem>>>(pQ, pK, pV, pAtt);

    gemm_mma_kernel<<<gg, 256>>>(pAtt, wo_w, wo_b, out, 0);
}

// round 4
// speedup vs baseline: 3.0947x; 1.4495x over previous
#include <cuda_runtime.h>
#include <cuda_bf16.h>
#include <math.h>
#include <cstdint>

constexpr int Bc = 4;
constexpr int Lc = 2048;
constexpr int Dd = 1024;
constexpr int Hh = 16;
constexpr int DK = 64;
constexpr int Mtok = Bc * Lc;   // 8192

// ---------------- scratch ----------------
__device__ float g_Q[Bc * Hh * Lc * DK];   // [B,H,L,DK]
__device__ float g_K[Bc * Hh * Lc * DK];
__device__ float g_V[Bc * Hh * Lc * DK];
__device__ float g_att[Bc * Lc * Dd];      // [B,L,D]

// ---------------- helpers ----------------
__device__ __forceinline__ uint32_t f2tf32(float f) {
    uint32_t r;
    asm("cvt.rna.tf32.f32 %0, %1;" : "=r"(r) : "f"(f));
    return r;
}

__device__ __forceinline__ void mma_tf32(float* d, const uint32_t* a, const uint32_t* b) {
    asm volatile(
        "mma.sync.aligned.m16n8k8.row.col.f32.tf32.tf32.f32 "
        "{%0,%1,%2,%3}, {%4,%5,%6,%7}, {%8,%9}, {%0,%1,%2,%3};\n"
        : "+f"(d[0]), "+f"(d[1]), "+f"(d[2]), "+f"(d[3])
        : "r"(a[0]), "r"(a[1]), "r"(a[2]), "r"(a[3]), "r"(b[0]), "r"(b[1]));
}

__device__ __forceinline__ float fcomp(const float4& v, int j) {
    return (j == 0) ? v.x : (j == 1) ? v.y : (j == 2) ? v.z : v.w;
}

// =====================================================================
// GEMM: C[m,n] = X[m,:] . W[n,:] + bias[n]
// CTA tile 256x128, 8 warps (4m x 2n), warp tile 64x64, BK=32, tf32 mma.
// Interleaved k-layout, 32-word rows, chunk swizzle ^ (row&7).
//   pos(c) = (c&3)*8 + (c>>2); chunk = (c&3)*2 + (c>>4); word = (c>>2)&3
// mode 0: out[m*1024+n]; mode 1: out in [B,H,L,DK]
// =====================================================================
constexpr int GEMM_SMEM_BYTES = (2 * 256 * 32 + 2 * 128 * 32) * 4;  // 98304

__global__ void __launch_bounds__(256) gemm_mma_kernel(const float* __restrict__ X,
                                                       const float* __restrict__ W,
                                                       const float* __restrict__ bias,
                                                       float* __restrict__ out,
                                                       int mode)
{
    extern __shared__ uint32_t sg[];
    uint32_t* As = sg;                  // [2][256][32]
    uint32_t* Bs = sg + 2 * 256 * 32;   // [2][128][32]

    const int tid  = threadIdx.x;
    const int w    = tid >> 5;
    const int lane = tid & 31;
    const int gid  = lane >> 2;
    const int t4   = lane & 3;

    const int m0 = blockIdx.y * 256;
    const int n0 = blockIdx.x * 128;
    const int wm = (w >> 1) * 64;
    const int wn = (w & 1) * 64;

    const int lr = tid >> 3;   // 0..31 loader row base
    const int lc = tid & 7;    // float4 col index

    float acc[4][8][4] = {};

    float4 va[8], vb[4];

    // gmem load of k-tile kt
    auto ldA = [&](int kt) {
        const float* p = X + (size_t)(m0 + lr) * Dd + kt * 32 + lc * 4;
        #pragma unroll
        for (int i = 0; i < 8; i++)
            va[i] = *(const float4*)(p + (size_t)(i * 32) * Dd);
    };
    auto ldB = [&](int kt) {
        const float* p = W + (size_t)(n0 + lr) * Dd + kt * 32 + lc * 4;
        #pragma unroll
        for (int i = 0; i < 4; i++)
            vb[i] = *(const float4*)(p + (size_t)(i * 32) * Dd);
    };
    // interleaved+swizzled store of staged regs
    auto stA = [&](int buf) {
        #pragma unroll
        for (int i = 0; i < 8; i++) {
            const int row = lr + 32 * i;
            const int r7 = row & 7;
            uint32_t* base = As + buf * 256 * 32 + row * 32;
            #pragma unroll
            for (int j = 0; j < 4; j++) {
                const int chunk = 2 * j + (lc >> 2);
                base[((chunk ^ r7) << 2) + (lc & 3)] = f2tf32(fcomp(va[i], j));
            }
        }
    };
    auto stB = [&](int buf) {
        #pragma unroll
        for (int i = 0; i < 4; i++) {
            const int row = lr + 32 * i;
            const int r7 = row & 7;
            uint32_t* base = Bs + buf * 128 * 32 + row * 32;
            #pragma unroll
            for (int j = 0; j < 4; j++) {
                const int chunk = 2 * j + (lc >> 2);
                base[((chunk ^ r7) << 2) + (lc & 3)] = f2tf32(fcomp(vb[i], j));
            }
        }
    };

    ldA(0); ldB(0);
    stA(0); stB(0);
    __syncthreads();

    for (int kt = 0; kt < 32; kt++) {
        const int buf = kt & 1;
        if (kt < 31) { ldA(kt + 1); ldB(kt + 1); }

        const uint32_t* A = As + buf * 256 * 32;
        const uint32_t* B = Bs + buf * 128 * 32;

        #pragma unroll
        for (int fi = 0; fi < 2; fi++) {
            const int ch = 2 * t4 + fi;
            uint4 bb[8];
            #pragma unroll
            for (int tn = 0; tn < 8; tn++) {
                const int rn = wn + tn * 8 + gid;
                bb[tn] = *(const uint4*)(B + rn * 32 + ((ch ^ gid) << 2));
            }
            #pragma unroll
            for (int tm = 0; tm < 4; tm++) {
                const int rl = wm + tm * 16 + gid;
                uint4 aL = *(const uint4*)(A + rl * 32 + ((ch ^ gid) << 2));
                uint4 aH = *(const uint4*)(A + (rl + 8) * 32 + ((ch ^ gid) << 2));
                uint32_t af0[4] = {aL.x, aH.x, aL.y, aH.y};
                uint32_t af1[4] = {aL.z, aH.z, aL.w, aH.w};
                #pragma unroll
                for (int tn = 0; tn < 8; tn++) {
                    uint32_t bf0[2] = {bb[tn].x, bb[tn].y};
                    uint32_t bf1[2] = {bb[tn].z, bb[tn].w};
                    mma_tf32(acc[tm][tn], af0, bf0);
                    mma_tf32(acc[tm][tn], af1, bf1);
                }
            }
        }

        if (kt < 31) { stA(buf ^ 1); stB(buf ^ 1); }
        __syncthreads();
    }

    // epilogue
    #pragma unroll
    for (int tm = 0; tm < 4; tm++) {
        const int r0 = m0 + wm + tm * 16 + gid;
        const int r1 = r0 + 8;
        #pragma unroll
        for (int tn = 0; tn < 8; tn++) {
            const int cc = n0 + wn + tn * 8 + t4 * 2;
            const float bv0 = __ldg(bias + cc);
            const float bv1 = __ldg(bias + cc + 1);
            float2 v0, v1;
            v0.x = acc[tm][tn][0] + bv0;  v0.y = acc[tm][tn][1] + bv1;
            v1.x = acc[tm][tn][2] + bv0;  v1.y = acc[tm][tn][3] + bv1;
            if (mode == 0) {
                *(float2*)(out + (size_t)r0 * Dd + cc) = v0;
                *(float2*)(out + (size_t)r1 * Dd + cc) = v1;
            } else {
                const int h = cc >> 6, dk = cc & 63;
                {
                    const int b = r0 >> 11, l = r0 & 2047;
                    *(float2*)(out + (((size_t)(b * Hh + h) * Lc + l) << 6) + dk) = v0;
                }
                {
                    const int b = r1 >> 11, l = r1 & 2047;
                    *(float2*)(out + (((size_t)(b * Hh + h) * Lc + l) << 6) + dk) = v1;
                }
            }
        }
    }
}

// =====================================================================
// Causal flash attention, tf32 mma.
// CTA: 128 q-rows x 32-key tiles. 256 threads, 8 warps (4m x 2n).
//  QK: warp 32q x 16k, dk=64 (fi 0..3);  PV: warp 32q x 32d, keys=32 (fi 0..1)
// Layouts (all chunk-swizzled by row&7):
//  Qs : 128 rows x 64 words, pos64:  chunk=(c&3)*4+(c>>4)
//  Ks : 32 rows x 64 words,  same
//  Vt : 64 d-rows x 32 words (keys), pos32: chunk=(c&3)*2+(c>>4)
//  Ss : 128 rows x 32 words (f32 scores -> tf32 P), pos32
// =====================================================================
constexpr int ATTN_SMEM_BYTES = (128 * 64 + 32 * 64 + 64 * 32 + 128 * 32) * 4 + 3 * 128 * 4;

__global__ void __launch_bounds__(256, 2) attn_mma_kernel(const float* __restrict__ Qg,
                                                          const float* __restrict__ Kg,
                                                          const float* __restrict__ Vg,
                                                          float* __restrict__ att)
{
    extern __shared__ uint32_t sa[];
    uint32_t* Qs = sa;                    // 128*64
    uint32_t* Ks = Qs + 128 * 64;         // 32*64
    uint32_t* Vt = Ks + 32 * 64;          // 64*32
    float*    Ss = (float*)(Vt + 64 * 32);// 128*32
    float* m_sh = Ss + 128 * 32;
    float* l_sh = m_sh + 128;
    float* a_sh = l_sh + 128;

    const int tid  = threadIdx.x;
    const int w    = tid >> 5;
    const int lane = tid & 31;
    const int gid  = lane >> 2;
    const int t4   = lane & 3;

    const int q0 = blockIdx.x * 128;
    const int h  = blockIdx.y;
    const int b  = blockIdx.z;

    const int wm  = (w >> 1) * 32;   // q-row base
    const int wnK = (w & 1) * 16;    // QK key base
    const int wnV = (w & 1) * 32;    // PV d base

    const size_t base = (size_t)(b * Hh + h) * Lc * DK;
    const float* Qbh = Qg + base;
    const float* Kbh = Kg + base;
    const float* Vbh = Vg + base;

    // ---- load Q tile (scaled, tf32, interleaved) : 2 threads per row ----
    {
        const int row = tid >> 1;
        const int hh  = tid & 1;
        const float* p = Qbh + (size_t)(q0 + row) * DK + hh * 32;
        float4 v[8];
        #pragma unroll
        for (int i = 0; i < 8; i++) {
            v[i] = *(const float4*)(p + 4 * i);
            v[i].x *= 0.125f; v[i].y *= 0.125f; v[i].z *= 0.125f; v[i].w *= 0.125f;
        }
        uint32_t* qb = Qs + row * 64;
        const int r7 = row & 7;
        #pragma unroll
        for (int s = 0; s < 4; s++)
            #pragma unroll
            for (int bb2 = 0; bb2 < 2; bb2++) {
                const int chunk = 4 * s + 2 * hh + bb2;
                uint4 u;
                u.x = f2tf32(fcomp(v[4 * bb2 + 0], s));
                u.y = f2tf32(fcomp(v[4 * bb2 + 1], s));
                u.z = f2tf32(fcomp(v[4 * bb2 + 2], s));
                u.w = f2tf32(fcomp(v[4 * bb2 + 3], s));
                *(uint4*)(qb + ((chunk ^ r7) << 2)) = u;
            }
    }
    if (tid < 128) { m_sh[tid] = -3.0e38f; l_sh[tid] = 0.0f; }

    float o[2][4][4] = {};
    __syncthreads();

    const int ntiles = q0 / 32 + 4;
    for (int t = 0; t < ntiles; t++) {
        const int k0 = t * 32;

        // ---- load K (threads 0..127) and V transposed (threads 128..255) ----
        if (tid < 128) {
            const int row = tid >> 2;       // key row 0..31
            const int qtr = tid & 3;
            const float* p = Kbh + (size_t)(k0 + row) * DK + qtr * 16;
            float4 u[4];
            #pragma unroll
            for (int i = 0; i < 4; i++) u[i] = *(const float4*)(p + 4 * i);
            uint32_t* kb = Ks + row * 64;
            const int r7 = row & 7;
            #pragma unroll
            for (int s = 0; s < 4; s++) {
                const int chunk = 4 * s + qtr;
                uint4 uu;
                uu.x = f2tf32(fcomp(u[0], s));
                uu.y = f2tf32(fcomp(u[1], s));
                uu.z = f2tf32(fcomp(u[2], s));
                uu.w = f2tf32(fcomp(u[3], s));
                *(uint4*)(kb + ((chunk ^ r7) << 2)) = uu;
            }
        } else {
            const int t2  = tid - 128;
            const int kr  = t2 >> 2;        // key row 0..31
            const int cq  = t2 & 3;         // d quarter
            const float* p = Vbh + (size_t)(k0 + kr) * DK + cq * 16;
            const int pos = (kr & 3) * 8 + (kr >> 2);
            const int pch = pos >> 2, pwd = pos & 3;
            #pragma unroll
            for (int i = 0; i < 4; i++) {
                float4 u = *(const float4*)(p + 4 * i);
                #pragma unroll
                for (int j = 0; j < 4; j++) {
                    const int d = cq * 16 + 4 * i + j;
                    Vt[d * 32 + ((pch ^ (d & 7)) << 2) + pwd] = f2tf32(fcomp(u, j));
                }
            }
        }
        __syncthreads();

        // ---- QK mma ----
        float sfr[2][2][4] = {};
        #pragma unroll
        for (int fi = 0; fi < 4; fi++) {
            const int ch = 4 * t4 + fi;
            uint4 kb[2];
            #pragma unroll
            for (int tn = 0; tn < 2; tn++) {
                const int rn = wnK + tn * 8 + gid;
                kb[tn] = *(const uint4*)(Ks + rn * 64 + ((ch ^ gid) << 2));
            }
            #pragma unroll
            for (int tm = 0; tm < 2; tm++) {
                const int rl = wm + tm * 16 + gid;
                uint4 aL = *(const uint4*)(Qs + rl * 64 + ((ch ^ gid) << 2));
                uint4 aH = *(const uint4*)(Qs + (rl + 8) * 64 + ((ch ^ gid) << 2));
                uint32_t af0[4] = {aL.x, aH.x, aL.y, aH.y};
                uint32_t af1[4] = {aL.z, aH.z, aL.w, aH.w};
                #pragma unroll
                for (int tn = 0; tn < 2; tn++) {
                    uint32_t bf0[2] = {kb[tn].x, kb[tn].y};
                    uint32_t bf1[2] = {kb[tn].z, kb[tn].w};
                    mma_tf32(sfr[tm][tn], af0, bf0);
                    mma_tf32(sfr[tm][tn], af1, bf1);
                }
            }
        }
        // store S (f32) interleaved
        #pragma unroll
        for (int tm = 0; tm < 2; tm++) {
            const int rl = wm + tm * 16 + gid;
            #pragma unroll
            for (int tn = 0; tn < 2; tn++) {
                #pragma unroll
                for (int e = 0; e < 2; e++) {
                    const int col = wnK + tn * 8 + 2 * t4 + e;
                    const int pos = (col & 3) * 8 + (col >> 2);
                    const int wd  = ((pos >> 2) ^ gid) * 4 + (pos & 3);
                    Ss[rl * 32 + wd]       = sfr[tm][tn][e];
                    Ss[(rl + 8) * 32 + wd] = sfr[tm][tn][2 + e];
                }
            }
        }
        __syncthreads();

        // ---- online softmax: 2 threads per row ----
        {
            const int row = tid >> 1;
            const int qd  = tid & 1;
            const int grow = q0 + row;
            const int r7 = row & 7;
            const float mold = m_sh[row];
            float vals[16];
            float mx = -3.0e38f;
            #pragma unroll
            for (int j = 0; j < 16; j++) {
                const int c = qd * 16 + j;
                const int pos = (c & 3) * 8 + (c >> 2);
                const int wd  = ((pos >> 2) ^ r7) * 4 + (pos & 3);
                const float sv = Ss[row * 32 + wd];
                const bool ok = (k0 + c) <= grow;
                vals[j] = ok ? sv : -3.0e38f;
                if (ok) mx = fmaxf(mx, sv);
            }
            mx = fmaxf(mx, __shfl_xor_sync(0xffffffff, mx, 1));
            const float mnew = fmaxf(mold, mx);
            float ps = 0.0f;
            #pragma unroll
            for (int j = 0; j < 16; j++) {
                const int c = qd * 16 + j;
                const int pos = (c & 3) * 8 + (c >> 2);
                const int wd  = ((pos >> 2) ^ r7) * 4 + (pos & 3);
                const bool ok = (k0 + c) <= grow;
                const float p = ok ? __expf(vals[j] - mnew) : 0.0f;
                ps += p;
                ((uint32_t*)Ss)[row * 32 + wd] = f2tf32(p);
            }
            ps += __shfl_xor_sync(0xffffffff, ps, 1);
            if (qd == 0) {
                const float alpha = __expf(mold - mnew);
                l_sh[row] = l_sh[row] * alpha + ps;
                m_sh[row] = mnew;
                a_sh[row] = alpha;
            }
        }
        __syncthreads();

        // ---- rescale O, then O += P V ----
        #pragma unroll
        for (int tm = 0; tm < 2; tm++) {
            const float a0 = a_sh[wm + tm * 16 + gid];
            const float a1 = a_sh[wm + tm * 16 + gid + 8];
            #pragma unroll
            for (int tn = 0; tn < 4; tn++) {
                o[tm][tn][0] *= a0; o[tm][tn][1] *= a0;
                o[tm][tn][2] *= a1; o[tm][tn][3] *= a1;
            }
        }
        const uint32_t* Su = (const uint32_t*)Ss;
        #pragma unroll
        for (int fi = 0; fi < 2; fi++) {
            const int ch = 2 * t4 + fi;
            uint4 vbf[4];
            #pragma unroll
            for (int tn = 0; tn < 4; tn++) {
                const int dn = wnV + tn * 8 + gid;
                vbf[tn] = *(const uint4*)(Vt + dn * 32 + ((ch ^ gid) << 2));
            }
            #pragma unroll
            for (int tm = 0; tm < 2; tm++) {
                const int rl = wm + tm * 16 + gid;
                uint4 pL = *(const uint4*)(Su + rl * 32 + ((ch ^ gid) << 2));
                uint4 pH = *(const uint4*)(Su + (rl + 8) * 32 + ((ch ^ gid) << 2));
                uint32_t af0[4] = {pL.x, pH.x, pL.y, pH.y};
                uint32_t af1[4] = {pL.z, pH.z, pL.w, pH.w};
                #pragma unroll
                for (int tn = 0; tn < 4; tn++) {
                    uint32_t bf0[2] = {vbf[tn].x, vbf[tn].y};
                    uint32_t bf1[2] = {vbf[tn].z, vbf[tn].w};
                    mma_tf32(o[tm][tn], af0, bf0);
                    mma_tf32(o[tm][tn], af1, bf1);
                }
            }
        }
        __syncthreads();
    }

    // ---- write normalized output to [B,L,D] ----
    #pragma unroll
    for (int tm = 0; tm < 2; tm++) {
        const int r0 = q0 + wm + tm * 16 + gid;
        const int r1 = r0 + 8;
        const float inv0 = 1.0f / l_sh[wm + tm * 16 + gid];
        const float inv1 = 1.0f / l_sh[wm + tm * 16 + gid + 8];
        #pragma unroll
        for (int tn = 0; tn < 4; tn++) {
            const int cc = wnV + tn * 8 + 2 * t4;
            float2 v0, v1;
            v0.x = o[tm][tn][0] * inv0; v0.y = o[tm][tn][1] * inv0;
            v1.x = o[tm][tn][2] * inv1; v1.y = o[tm][tn][3] * inv1;
            *(float2*)(att + ((size_t)(b * Lc + r0)) * Dd + h * DK + cc) = v0;
            *(float2*)(att + ((size_t)(b * Lc + r1)) * Dd + h * DK + cc) = v1;
        }
    }
}

// ---------------- launch ----------------
extern "C" void kernel_launch(void* const* d_in, const int* in_sizes, int n_in,
                              void* d_out, int out_size)
{
    const float* q    = (const float*)d_in[0];
    const float* k    = (const float*)d_in[1];
    const float* v    = (const float*)d_in[2];
    const float* wq_w = (const float*)d_in[3];
    const float* wq_b = (const float*)d_in[4];
    const float* wk_w = (const float*)d_in[5];
    const float* wk_b = (const float*)d_in[6];
    const float* wv_w = (const float*)d_in[7];
    const float* wv_b = (const float*)d_in[8];
    const float* wo_w = (const float*)d_in[9];
    const float* wo_b = (const float*)d_in[10];
    float* out = (float*)d_out;

    float *pQ, *pK, *pV, *pAtt;
    cudaGetSymbolAddress((void**)&pQ,   g_Q);
    cudaGetSymbolAddress((void**)&pK,   g_K);
    cudaGetSymbolAddress((void**)&pV,   g_V);
    cudaGetSymbolAddress((void**)&pAtt, g_att);

    cudaFuncSetAttribute(gemm_mma_kernel, cudaFuncAttributeMaxDynamicSharedMemorySize, GEMM_SMEM_BYTES);
    cudaFuncSetAttribute(attn_mma_kernel, cudaFuncAttributeMaxDynamicSharedMemorySize, ATTN_SMEM_BYTES);

    dim3 gg(Dd / 128, Mtok / 256);   // (8, 32)

    gemm_mma_kernel<<<gg, 256, GEMM_SMEM_BYTES>>>(q, wq_w, wq_b, pQ, 1);
    gemm_mma_kernel<<<gg, 256, GEMM_SMEM_BYTES>>>(k, wk_w, wk_b, pK, 1);
    gemm_mma_kernel<<<gg, 256, GEMM_SMEM_BYTES>>>(v, wv_w, wv_b, pV, 1);

    dim3 ga(Lc / 128, Hh, Bc);       // (16, 16, 4)
    attn_mma_kernel<<<ga, 256, ATTN_SMEM_BYTES>>>(pQ, pK, pV, pAtt);

    gemm_mma_kernel<<<gg, 256, GEMM_SMEM_BYTES>>>(pAtt, wo_w, wo_b, out, 0);
}

// round 5
// speedup vs baseline: 3.3809x; 1.0925x over previous
#include <cuda_runtime.h>
#include <cuda_bf16.h>
#include <math.h>
#include <cstdint>

constexpr int Bc = 4;
constexpr int Lc = 2048;
constexpr int Dd = 1024;
constexpr int Hh = 16;
constexpr int DK = 64;
constexpr int Mtok = Bc * Lc;   // 8192

// ---------------- scratch ----------------
__device__ float g_Q[Bc * Hh * Lc * DK];   // [B,H,L,DK]
__device__ float g_K[Bc * Hh * Lc * DK];
__device__ float g_V[Bc * Hh * Lc * DK];
__device__ float g_att[Bc * Lc * Dd];      // [B,L,D]

// ---------------- helpers ----------------
__device__ __forceinline__ uint32_t f2tf32(float f) {
    uint32_t r;
    asm("cvt.rna.tf32.f32 %0, %1;" : "=r"(r) : "f"(f));
    return r;
}

__device__ __forceinline__ void mma_tf32(float* d, const uint32_t* a, const uint32_t* b) {
    asm volatile(
        "mma.sync.aligned.m16n8k8.row.col.f32.tf32.tf32.f32 "
        "{%0,%1,%2,%3}, {%4,%5,%6,%7}, {%8,%9}, {%0,%1,%2,%3};\n"
        : "+f"(d[0]), "+f"(d[1]), "+f"(d[2]), "+f"(d[3])
        : "r"(a[0]), "r"(a[1]), "r"(a[2]), "r"(a[3]), "r"(b[0]), "r"(b[1]));
}

__device__ __forceinline__ float fcomp(const float4& v, int j) {
    return (j == 0) ? v.x : (j == 1) ? v.y : (j == 2) ? v.z : v.w;
}

// =====================================================================
// GEMM: C[m,n] = X[m,:] . W[n,:] + bias[n]
// CTA 128x128, 8 warps (2m x 4n), warp tile 64x32, BK=32, 2 CTAs/SM.
// =====================================================================
constexpr int GEMM_SMEM_BYTES = (2 * 128 * 32 + 2 * 128 * 32) * 4;  // 65536

__global__ void __launch_bounds__(256, 2) gemm_mma_kernel(const float* __restrict__ X,
                                                          const float* __restrict__ W,
                                                          const float* __restrict__ bias,
                                                          float* __restrict__ out,
                                                          int mode)
{
    extern __shared__ uint32_t sg[];
    uint32_t* As = sg;                  // [2][128][32]
    uint32_t* Bs = sg + 2 * 128 * 32;   // [2][128][32]

    const int tid  = threadIdx.x;
    const int w    = tid >> 5;
    const int lane = tid & 31;
    const int gid  = lane >> 2;
    const int t4   = lane & 3;

    const int m0 = blockIdx.y * 128;
    const int n0 = blockIdx.x * 128;
    const int wm = (w >> 2) * 64;   // 2 m-groups
    const int wn = (w & 3) * 32;    // 4 n-groups

    const int lr = tid >> 3;   // 0..31
    const int lc = tid & 7;

    float acc[4][4][4] = {};
    float4 va[4], vb[4];

    auto ldA = [&](int kt) {
        const float* p = X + (size_t)(m0 + lr) * Dd + kt * 32 + lc * 4;
        #pragma unroll
        for (int i = 0; i < 4; i++)
            va[i] = *(const float4*)(p + (size_t)(i * 32) * Dd);
    };
    auto ldB = [&](int kt) {
        const float* p = W + (size_t)(n0 + lr) * Dd + kt * 32 + lc * 4;
        #pragma unroll
        for (int i = 0; i < 4; i++)
            vb[i] = *(const float4*)(p + (size_t)(i * 32) * Dd);
    };
    auto stAB = [&](int buf) {
        #pragma unroll
        for (int i = 0; i < 4; i++) {
            const int row = lr + 32 * i;
            const int r7 = row & 7;
            uint32_t* ba = As + buf * 128 * 32 + row * 32;
            uint32_t* bb = Bs + buf * 128 * 32 + row * 32;
            #pragma unroll
            for (int j = 0; j < 4; j++) {
                const int chunk = 2 * j + (lc >> 2);
                const int off = ((chunk ^ r7) << 2) + (lc & 3);
                ba[off] = f2tf32(fcomp(va[i], j));
                bb[off] = f2tf32(fcomp(vb[i], j));
            }
        }
    };

    ldA(0); ldB(0);
    stAB(0);
    __syncthreads();

    for (int kt = 0; kt < 32; kt++) {
        const int buf = kt & 1;
        if (kt < 31) { ldA(kt + 1); ldB(kt + 1); }

        const uint32_t* A = As + buf * 128 * 32;
        const uint32_t* B = Bs + buf * 128 * 32;

        #pragma unroll
        for (int fi = 0; fi < 2; fi++) {
            const int ch = 2 * t4 + fi;
            uint4 bbf[4];
            #pragma unroll
            for (int tn = 0; tn < 4; tn++) {
                const int rn = wn + tn * 8 + gid;
                bbf[tn] = *(const uint4*)(B + rn * 32 + ((ch ^ gid) << 2));
            }
            #pragma unroll
            for (int tm = 0; tm < 4; tm++) {
                const int rl = wm + tm * 16 + gid;
                uint4 aL = *(const uint4*)(A + rl * 32 + ((ch ^ gid) << 2));
                uint4 aH = *(const uint4*)(A + (rl + 8) * 32 + ((ch ^ gid) << 2));
                uint32_t af0[4] = {aL.x, aH.x, aL.y, aH.y};
                uint32_t af1[4] = {aL.z, aH.z, aL.w, aH.w};
                #pragma unroll
                for (int tn = 0; tn < 4; tn++) {
                    uint32_t bf0[2] = {bbf[tn].x, bbf[tn].y};
                    uint32_t bf1[2] = {bbf[tn].z, bbf[tn].w};
                    mma_tf32(acc[tm][tn], af0, bf0);
                    mma_tf32(acc[tm][tn], af1, bf1);
                }
            }
        }

        if (kt < 31) stAB(buf ^ 1);
        __syncthreads();
    }

    // epilogue
    #pragma unroll
    for (int tm = 0; tm < 4; tm++) {
        const int r0 = m0 + wm + tm * 16 + gid;
        const int r1 = r0 + 8;
        #pragma unroll
        for (int tn = 0; tn < 4; tn++) {
            const int cc = n0 + wn + tn * 8 + t4 * 2;
            const float bv0 = __ldg(bias + cc);
            const float bv1 = __ldg(bias + cc + 1);
            float2 v0, v1;
            v0.x = acc[tm][tn][0] + bv0;  v0.y = acc[tm][tn][1] + bv1;
            v1.x = acc[tm][tn][2] + bv0;  v1.y = acc[tm][tn][3] + bv1;
            if (mode == 0) {
                *(float2*)(out + (size_t)r0 * Dd + cc) = v0;
                *(float2*)(out + (size_t)r1 * Dd + cc) = v1;
            } else {
                const int h = cc >> 6, dk = cc & 63;
                {
                    const int b = r0 >> 11, l = r0 & 2047;
                    *(float2*)(out + (((size_t)(b * Hh + h) * Lc + l) << 6) + dk) = v0;
                }
                {
                    const int b = r1 >> 11, l = r1 & 2047;
                    *(float2*)(out + (((size_t)(b * Hh + h) * Lc + l) << 6) + dk) = v1;
                }
            }
        }
    }
}

// =====================================================================
// Causal flash attention, tf32 mma, register-resident softmax.
// CTA: 128 q-rows; warp w owns q rows [q0+16w, q0+16w+16), full 32-key width.
// Q stays in registers (A-frags). One __syncthreads per 32-key tile.
// Smem: double-buffered Ks[2][32x64 words], Vt[2][64x32 words] (swizzled).
// =====================================================================
constexpr int ATTN_SMEM_BYTES = (2 * 32 * 64 + 2 * 64 * 32) * 4;  // 32768

__global__ void __launch_bounds__(256, 2) attn_mma_kernel(const float* __restrict__ Qg,
                                                          const float* __restrict__ Kg,
                                                          const float* __restrict__ Vg,
                                                          float* __restrict__ att)
{
    extern __shared__ uint32_t sa[];
    uint32_t* Ks = sa;                 // [2][32*64]
    uint32_t* Vt = sa + 2 * 32 * 64;   // [2][64*32]

    const int tid  = threadIdx.x;
    const int w    = tid >> 5;
    const int lane = tid & 31;
    const int gid  = lane >> 2;
    const int t4   = lane & 3;

    const int q0 = blockIdx.x * 128;
    const int h  = blockIdx.y;
    const int b  = blockIdx.z;

    const int wq    = q0 + w * 16;     // warp q-row base
    const int qrow0 = wq + gid;        // row g   (row g+8 = qrow0+8)

    const size_t base = (size_t)(b * Hh + h) * Lc * DK;
    const float* Qbh = Qg + base;
    const float* Kbh = Kg + base;
    const float* Vbh = Vg + base;

    // ---- Q fragments in registers (pre-scaled, tf32) ----
    uint32_t qf[8][4];
    {
        const float* qp0 = Qbh + (size_t)qrow0 * DK;
        const float* qp1 = qp0 + 8 * DK;
        #pragma unroll
        for (int kc = 0; kc < 8; kc++) {
            const int c0 = kc * 8 + t4, c1 = c0 + 4;
            qf[kc][0] = f2tf32(__ldg(qp0 + c0) * 0.125f);
            qf[kc][1] = f2tf32(__ldg(qp1 + c0) * 0.125f);
            qf[kc][2] = f2tf32(__ldg(qp0 + c1) * 0.125f);
            qf[kc][3] = f2tf32(__ldg(qp1 + c1) * 0.125f);
        }
    }

    float Oacc[8][4] = {};
    float mrow0 = -3.0e38f, mrow1 = -3.0e38f;
    float lrow0 = 0.0f,     lrow1 = 0.0f;

    // ---- K/V tile loader (threads 0..127: K, 128..255: V-transposed) ----
    const bool isK = tid < 128;
    const int  lrw = (tid & 127) >> 2;   // key row 0..31
    const int  lqt = tid & 3;            // dk quarter
    const float* lp = (isK ? Kbh : Vbh) + (size_t)lrw * DK + lqt * 16;

    float4 stg[4];
    auto ldTile = [&](int k0) {
        const float* p = lp + (size_t)k0 * DK;
        #pragma unroll
        for (int i = 0; i < 4; i++) stg[i] = *(const float4*)(p + 4 * i);
    };
    auto stTile = [&](int buf) {
        if (isK) {
            uint32_t* kb = Ks + buf * 2048 + lrw * 64;
            const int r7 = lrw & 7;
            #pragma unroll
            for (int s = 0; s < 4; s++) {
                const int chunk = 4 * s + lqt;
                uint4 u;
                u.x = f2tf32(fcomp(stg[0], s));
                u.y = f2tf32(fcomp(stg[1], s));
                u.z = f2tf32(fcomp(stg[2], s));
                u.w = f2tf32(fcomp(stg[3], s));
                *(uint4*)(kb + ((chunk ^ r7) << 2)) = u;
            }
        } else {
            uint32_t* vb = Vt + buf * 2048;
            const int pos = (lrw & 3) * 8 + (lrw >> 2);
            const int pch = pos >> 2, pwd = pos & 3;
            #pragma unroll
            for (int i = 0; i < 4; i++) {
                #pragma unroll
                for (int j = 0; j < 4; j++) {
                    const int d = lqt * 16 + 4 * i + j;
                    vb[d * 32 + ((pch ^ (d & 7)) << 2) + pwd] = f2tf32(fcomp(stg[i], j));
                }
            }
        }
    };

    ldTile(0);
    stTile(0);
    __syncthreads();

    const int ntiles = q0 / 32 + 4;
    const int src0 = (lane & ~3) + (t4 >> 1);
    const int src2 = src0 + 2;
    const bool odd = (t4 & 1) != 0;

    for (int t = 0; t < ntiles; t++) {
        const int k0  = t * 32;
        const int buf = t & 1;
        if (t + 1 < ntiles) ldTile((t + 1) * 32);

        if (k0 <= wq + 15) {   // warp-uniform: tile not fully masked for this warp
            // ---- S = Q' K^T (registers) ----
            float s[4][4] = {};
            const uint32_t* Kb = Ks + buf * 2048;
            #pragma unroll
            for (int fi = 0; fi < 4; fi++) {
                const int ch = 4 * t4 + fi;
                #pragma unroll
                for (int tn = 0; tn < 4; tn++) {
                    const int rn = tn * 8 + gid;
                    uint4 kb = *(const uint4*)(Kb + rn * 64 + ((ch ^ gid) << 2));
                    uint32_t bf0[2] = {kb.x, kb.y};
                    uint32_t bf1[2] = {kb.z, kb.w};
                    mma_tf32(s[tn], qf[2 * fi], bf0);
                    mma_tf32(s[tn], qf[2 * fi + 1], bf1);
                }
            }
            // ---- causal mask (only diagonal tiles) ----
            if (k0 + 31 > wq) {
                #pragma unroll
                for (int tn = 0; tn < 4; tn++) {
                    const int c = k0 + tn * 8 + 2 * t4;
                    if (c     > qrow0)     s[tn][0] = -3.0e38f;
                    if (c + 1 > qrow0)     s[tn][1] = -3.0e38f;
                    if (c     > qrow0 + 8) s[tn][2] = -3.0e38f;
                    if (c + 1 > qrow0 + 8) s[tn][3] = -3.0e38f;
                }
            }
            // ---- register softmax (quad shfl reductions) ----
            float mx0 = s[0][0], mx1 = s[0][2];
            #pragma unroll
            for (int tn = 0; tn < 4; tn++) {
                mx0 = fmaxf(mx0, fmaxf(s[tn][0], s[tn][1]));
                mx1 = fmaxf(mx1, fmaxf(s[tn][2], s[tn][3]));
            }
            mx0 = fmaxf(mx0, __shfl_xor_sync(0xffffffffu, mx0, 1));
            mx0 = fmaxf(mx0, __shfl_xor_sync(0xffffffffu, mx0, 2));
            mx1 = fmaxf(mx1, __shfl_xor_sync(0xffffffffu, mx1, 1));
            mx1 = fmaxf(mx1, __shfl_xor_sync(0xffffffffu, mx1, 2));
            const float mn0 = fmaxf(mrow0, mx0);
            const float mn1 = fmaxf(mrow1, mx1);

            uint32_t pb[4][4];
            float ps0 = 0.0f, ps1 = 0.0f;
            #pragma unroll
            for (int tn = 0; tn < 4; tn++) {
                float p0 = __expf(s[tn][0] - mn0);
                float p1 = __expf(s[tn][1] - mn0);
                float p2 = __expf(s[tn][2] - mn1);
                float p3 = __expf(s[tn][3] - mn1);
                ps0 += p0 + p1;
                ps1 += p2 + p3;
                pb[tn][0] = f2tf32(p0);
                pb[tn][1] = f2tf32(p1);
                pb[tn][2] = f2tf32(p2);
                pb[tn][3] = f2tf32(p3);
            }
            ps0 += __shfl_xor_sync(0xffffffffu, ps0, 1);
            ps0 += __shfl_xor_sync(0xffffffffu, ps0, 2);
            ps1 += __shfl_xor_sync(0xffffffffu, ps1, 1);
            ps1 += __shfl_xor_sync(0xffffffffu, ps1, 2);

            const float al0 = __expf(mrow0 - mn0);
            const float al1 = __expf(mrow1 - mn1);
            lrow0 = lrow0 * al0 + ps0;
            lrow1 = lrow1 * al1 + ps1;
            mrow0 = mn0;
            mrow1 = mn1;
            #pragma unroll
            for (int nd = 0; nd < 8; nd++) {
                Oacc[nd][0] *= al0; Oacc[nd][1] *= al0;
                Oacc[nd][2] *= al1; Oacc[nd][3] *= al1;
            }

            // ---- P C-frag -> A-frag via quad shuffles ----
            uint32_t pa[4][4];
            #pragma unroll
            for (int kc = 0; kc < 4; kc++) {
                uint32_t s00 = __shfl_sync(0xffffffffu, pb[kc][0], src0);
                uint32_t s01 = __shfl_sync(0xffffffffu, pb[kc][1], src0);
                uint32_t s10 = __shfl_sync(0xffffffffu, pb[kc][2], src0);
                uint32_t s11 = __shfl_sync(0xffffffffu, pb[kc][3], src0);
                uint32_t s20 = __shfl_sync(0xffffffffu, pb[kc][0], src2);
                uint32_t s21 = __shfl_sync(0xffffffffu, pb[kc][1], src2);
                uint32_t s30 = __shfl_sync(0xffffffffu, pb[kc][2], src2);
                uint32_t s31 = __shfl_sync(0xffffffffu, pb[kc][3], src2);
                pa[kc][0] = odd ? s01 : s00;
                pa[kc][1] = odd ? s11 : s10;
                pa[kc][2] = odd ? s21 : s20;
                pa[kc][3] = odd ? s31 : s30;
            }

            // ---- O += P V ----
            const uint32_t* Vb = Vt + buf * 2048;
            #pragma unroll
            for (int fi = 0; fi < 2; fi++) {
                const int ch = 2 * t4 + fi;
                #pragma unroll
                for (int nd = 0; nd < 8; nd++) {
                    const int dn = nd * 8 + gid;
                    uint4 vv = *(const uint4*)(Vb + dn * 32 + ((ch ^ gid) << 2));
                    uint32_t bf0[2] = {vv.x, vv.y};
                    uint32_t bf1[2] = {vv.z, vv.w};
                    mma_tf32(Oacc[nd], pa[2 * fi], bf0);
                    mma_tf32(Oacc[nd], pa[2 * fi + 1], bf1);
                }
            }
        }

        if (t + 1 < ntiles) stTile(buf ^ 1);
        __syncthreads();
    }

    // ---- write normalized output to [B,L,D] ----
    const float inv0 = 1.0f / lrow0;
    const float inv1 = 1.0f / lrow1;
    float* o0 = att + ((size_t)(b * Lc + qrow0))     * Dd + h * DK;
    float* o1 = att + ((size_t)(b * Lc + qrow0 + 8)) * Dd + h * DK;
    #pragma unroll
    for (int nd = 0; nd < 8; nd++) {
        const int cc = nd * 8 + 2 * t4;
        float2 v0, v1;
        v0.x = Oacc[nd][0] * inv0; v0.y = Oacc[nd][1] * inv0;
        v1.x = Oacc[nd][2] * inv1; v1.y = Oacc[nd][3] * inv1;
        *(float2*)(o0 + cc) = v0;
        *(float2*)(o1 + cc) = v1;
    }
}

// ---------------- launch ----------------
extern "C" void kernel_launch(void* const* d_in, const int* in_sizes, int n_in,
                              void* d_out, int out_size)
{
    const float* q    = (const float*)d_in[0];
    const float* k    = (const float*)d_in[1];
    const float* v    = (const float*)d_in[2];
    const float* wq_w = (const float*)d_in[3];
    const float* wq_b = (const float*)d_in[4];
    const float* wk_w = (const float*)d_in[5];
    const float* wk_b = (const float*)d_in[6];
    const float* wv_w = (const float*)d_in[7];
    const float* wv_b = (const float*)d_in[8];
    const float* wo_w = (const float*)d_in[9];
    const float* wo_b = (const float*)d_in[10];
    float* out = (float*)d_out;

    float *pQ, *pK, *pV, *pAtt;
    cudaGetSymbolAddress((void**)&pQ,   g_Q);
    cudaGetSymbolAddress((void**)&pK,   g_K);
    cudaGetSymbolAddress((void**)&pV,   g_V);
    cudaGetSymbolAddress((void**)&pAtt, g_att);

    cudaFuncSetAttribute(gemm_mma_kernel, cudaFuncAttributeMaxDynamicSharedMemorySize, GEMM_SMEM_BYTES);
    cudaFuncSetAttribute(attn_mma_kernel, cudaFuncAttributeMaxDynamicSharedMemorySize, ATTN_SMEM_BYTES);

    dim3 gg(Dd / 128, Mtok / 128);   // (8, 64)

    gemm_mma_kernel<<<gg, 256, GEMM_SMEM_BYTES>>>(q, wq_w, wq_b, pQ, 1);
    gemm_mma_kernel<<<gg, 256, GEMM_SMEM_BYTES>>>(k, wk_w, wk_b, pK, 1);
    gemm_mma_kernel<<<gg, 256, GEMM_SMEM_BYTES>>>(v, wv_w, wv_b, pV, 1);

    dim3 ga(Lc / 128, Hh, Bc);       // (16, 16, 4)
    attn_mma_kernel<<<ga, 256, ATTN_SMEM_BYTES>>>(pQ, pK, pV, pAtt);

    gemm_mma_kernel<<<gg, 256, GEMM_SMEM_BYTES>>>(pAtt, wo_w, wo_b, out, 0);
}

// round 6
// speedup vs baseline: 3.8190x; 1.1296x over previous
#include <cuda_runtime.h>
#include <cuda_bf16.h>
#include <math.h>
#include <cstdint>

constexpr int Bc = 4;
constexpr int Lc = 2048;
constexpr int Dd = 1024;
constexpr int Hh = 16;
constexpr int DK = 64;
constexpr int Mtok = Bc * Lc;   // 8192

// ---------------- scratch ----------------
__device__ float g_Q[Bc * Hh * Lc * DK];   // [B,H,L,DK]
__device__ float g_K[Bc * Hh * Lc * DK];
__device__ float g_V[Bc * Hh * Lc * DK];
__device__ float g_att[Bc * Lc * Dd];      // [B,L,D]

// ---------------- helpers ----------------
__device__ __forceinline__ uint32_t f2tf32(float f) {
    uint32_t r;
    asm("cvt.rna.tf32.f32 %0, %1;" : "=r"(r) : "f"(f));
    return r;
}

__device__ __forceinline__ void mma_tf32(float* d, const uint32_t* a, const uint32_t* b) {
    asm volatile(
        "mma.sync.aligned.m16n8k8.row.col.f32.tf32.tf32.f32 "
        "{%0,%1,%2,%3}, {%4,%5,%6,%7}, {%8,%9}, {%0,%1,%2,%3};\n"
        : "+f"(d[0]), "+f"(d[1]), "+f"(d[2]), "+f"(d[3])
        : "r"(a[0]), "r"(a[1]), "r"(a[2]), "r"(a[3]), "r"(b[0]), "r"(b[1]));
}

__device__ __forceinline__ float fcomp(const float4& v, int j) {
    return (j == 0) ? v.x : (j == 1) ? v.y : (j == 2) ? v.z : v.w;
}

// =====================================================================
// GEMM core (R4 shape): CTA 256x128, 8 warps (4m x 2n), warp 64x64, BK=32.
// C[m,n] = X[m,:] . W[n,:] + bias[n]
// mode 0: out[m*1024+n]; mode 1: out in [B,H,L,DK]
// =====================================================================
constexpr int GEMM_SMEM_BYTES = (2 * 256 * 32 + 2 * 128 * 32) * 4;  // 98304

__device__ __forceinline__ void gemm_core(const float* __restrict__ X,
                                          const float* __restrict__ W,
                                          const float* __restrict__ bias,
                                          float* __restrict__ out,
                                          int mode, int bx, int by,
                                          uint32_t* sg)
{
    uint32_t* As = sg;                  // [2][256][32]
    uint32_t* Bs = sg + 2 * 256 * 32;   // [2][128][32]

    const int tid  = threadIdx.x;
    const int w    = tid >> 5;
    const int lane = tid & 31;
    const int gid  = lane >> 2;
    const int t4   = lane & 3;

    const int m0 = by * 256;
    const int n0 = bx * 128;
    const int wm = (w >> 1) * 64;
    const int wn = (w & 1) * 64;

    const int lr = tid >> 3;   // 0..31
    const int lc = tid & 7;

    float acc[4][8][4] = {};
    float4 va[8], vb[4];

    auto ldA = [&](int kt) {
        const float* p = X + (size_t)(m0 + lr) * Dd + kt * 32 + lc * 4;
        #pragma unroll
        for (int i = 0; i < 8; i++)
            va[i] = *(const float4*)(p + (size_t)(i * 32) * Dd);
    };
    auto ldB = [&](int kt) {
        const float* p = W + (size_t)(n0 + lr) * Dd + kt * 32 + lc * 4;
        #pragma unroll
        for (int i = 0; i < 4; i++)
            vb[i] = *(const float4*)(p + (size_t)(i * 32) * Dd);
    };
    auto stA = [&](int buf) {
        #pragma unroll
        for (int i = 0; i < 8; i++) {
            const int row = lr + 32 * i;
            const int r7 = row & 7;
            uint32_t* base = As + buf * 256 * 32 + row * 32;
            #pragma unroll
            for (int j = 0; j < 4; j++) {
                const int chunk = 2 * j + (lc >> 2);
                base[((chunk ^ r7) << 2) + (lc & 3)] = f2tf32(fcomp(va[i], j));
            }
        }
    };
    auto stB = [&](int buf) {
        #pragma unroll
        for (int i = 0; i < 4; i++) {
            const int row = lr + 32 * i;
            const int r7 = row & 7;
            uint32_t* base = Bs + buf * 128 * 32 + row * 32;
            #pragma unroll
            for (int j = 0; j < 4; j++) {
                const int chunk = 2 * j + (lc >> 2);
                base[((chunk ^ r7) << 2) + (lc & 3)] = f2tf32(fcomp(vb[i], j));
            }
        }
    };

    ldA(0); ldB(0);
    stA(0); stB(0);
    __syncthreads();

    for (int kt = 0; kt < 32; kt++) {
        const int buf = kt & 1;
        if (kt < 31) { ldA(kt + 1); ldB(kt + 1); }

        const uint32_t* A = As + buf * 256 * 32;
        const uint32_t* B = Bs + buf * 128 * 32;

        #pragma unroll
        for (int fi = 0; fi < 2; fi++) {
            const int ch = 2 * t4 + fi;
            uint4 bb[8];
            #pragma unroll
            for (int tn = 0; tn < 8; tn++) {
                const int rn = wn + tn * 8 + gid;
                bb[tn] = *(const uint4*)(B + rn * 32 + ((ch ^ gid) << 2));
            }
            #pragma unroll
            for (int tm = 0; tm < 4; tm++) {
                const int rl = wm + tm * 16 + gid;
                uint4 aL = *(const uint4*)(A + rl * 32 + ((ch ^ gid) << 2));
                uint4 aH = *(const uint4*)(A + (rl + 8) * 32 + ((ch ^ gid) << 2));
                uint32_t af0[4] = {aL.x, aH.x, aL.y, aH.y};
                uint32_t af1[4] = {aL.z, aH.z, aL.w, aH.w};
                #pragma unroll
                for (int tn = 0; tn < 8; tn++) {
                    uint32_t bf0[2] = {bb[tn].x, bb[tn].y};
                    uint32_t bf1[2] = {bb[tn].z, bb[tn].w};
                    mma_tf32(acc[tm][tn], af0, bf0);
                    mma_tf32(acc[tm][tn], af1, bf1);
                }
            }
        }

        if (kt < 31) { stA(buf ^ 1); stB(buf ^ 1); }
        __syncthreads();
    }

    #pragma unroll
    for (int tm = 0; tm < 4; tm++) {
        const int r0 = m0 + wm + tm * 16 + gid;
        const int r1 = r0 + 8;
        #pragma unroll
        for (int tn = 0; tn < 8; tn++) {
            const int cc = n0 + wn + tn * 8 + t4 * 2;
            const float bv0 = __ldg(bias + cc);
            const float bv1 = __ldg(bias + cc + 1);
            float2 v0, v1;
            v0.x = acc[tm][tn][0] + bv0;  v0.y = acc[tm][tn][1] + bv1;
            v1.x = acc[tm][tn][2] + bv0;  v1.y = acc[tm][tn][3] + bv1;
            if (mode == 0) {
                *(float2*)(out + (size_t)r0 * Dd + cc) = v0;
                *(float2*)(out + (size_t)r1 * Dd + cc) = v1;
            } else {
                const int h = cc >> 6, dk = cc & 63;
                {
                    const int b = r0 >> 11, l = r0 & 2047;
                    *(float2*)(out + (((size_t)(b * Hh + h) * Lc + l) << 6) + dk) = v0;
                }
                {
                    const int b = r1 >> 11, l = r1 & 2047;
                    *(float2*)(out + (((size_t)(b * Hh + h) * Lc + l) << 6) + dk) = v1;
                }
            }
        }
    }
}

struct QKVArgs {
    const float* X[3];
    const float* W[3];
    const float* bias[3];
    float* out[3];
};

__global__ void __launch_bounds__(256) gemm_qkv_kernel(QKVArgs args)
{
    extern __shared__ uint32_t sg[];
    const int z = blockIdx.z;
    gemm_core(args.X[z], args.W[z], args.bias[z], args.out[z], 1,
              blockIdx.x, blockIdx.y, sg);
}

__global__ void __launch_bounds__(256) gemm_o_kernel(const float* __restrict__ X,
                                                     const float* __restrict__ W,
                                                     const float* __restrict__ bias,
                                                     float* __restrict__ out)
{
    extern __shared__ uint32_t sg[];
    gemm_core(X, W, bias, out, 0, blockIdx.x, blockIdx.y, sg);
}

// =====================================================================
// Causal flash attention, tf32 mma, register-resident softmax (R5) +
// LPT block ordering (longest q-blocks first).
// =====================================================================
constexpr int ATTN_SMEM_BYTES = (2 * 32 * 64 + 2 * 64 * 32) * 4;  // 32768

__global__ void __launch_bounds__(256, 2) attn_mma_kernel(const float* __restrict__ Qg,
                                                          const float* __restrict__ Kg,
                                                          const float* __restrict__ Vg,
                                                          float* __restrict__ att)
{
    extern __shared__ uint32_t sa[];
    uint32_t* Ks = sa;                 // [2][32*64]
    uint32_t* Vt = sa + 2 * 32 * 64;   // [2][64*32]

    const int tid  = threadIdx.x;
    const int w    = tid >> 5;
    const int lane = tid & 31;
    const int gid  = lane >> 2;
    const int t4   = lane & 3;

    const int qb = gridDim.x - 1 - blockIdx.x;   // LPT: longest first
    const int q0 = qb * 128;
    const int h  = blockIdx.y;
    const int b  = blockIdx.z;

    const int wq    = q0 + w * 16;
    const int qrow0 = wq + gid;

    const size_t base = (size_t)(b * Hh + h) * Lc * DK;
    const float* Qbh = Qg + base;
    const float* Kbh = Kg + base;
    const float* Vbh = Vg + base;

    // ---- Q fragments in registers (pre-scaled, tf32) ----
    uint32_t qf[8][4];
    {
        const float* qp0 = Qbh + (size_t)qrow0 * DK;
        const float* qp1 = qp0 + 8 * DK;
        #pragma unroll
        for (int kc = 0; kc < 8; kc++) {
            const int c0 = kc * 8 + t4, c1 = c0 + 4;
            qf[kc][0] = f2tf32(__ldg(qp0 + c0) * 0.125f);
            qf[kc][1] = f2tf32(__ldg(qp1 + c0) * 0.125f);
            qf[kc][2] = f2tf32(__ldg(qp0 + c1) * 0.125f);
            qf[kc][3] = f2tf32(__ldg(qp1 + c1) * 0.125f);
        }
    }

    float Oacc[8][4] = {};
    float mrow0 = -3.0e38f, mrow1 = -3.0e38f;
    float lrow0 = 0.0f,     lrow1 = 0.0f;

    const bool isK = tid < 128;
    const int  lrw = (tid & 127) >> 2;
    const int  lqt = tid & 3;
    const float* lp = (isK ? Kbh : Vbh) + (size_t)lrw * DK + lqt * 16;

    float4 stg[4];
    auto ldTile = [&](int k0) {
        const float* p = lp + (size_t)k0 * DK;
        #pragma unroll
        for (int i = 0; i < 4; i++) stg[i] = *(const float4*)(p + 4 * i);
    };
    auto stTile = [&](int buf) {
        if (isK) {
            uint32_t* kb = Ks + buf * 2048 + lrw * 64;
            const int r7 = lrw & 7;
            #pragma unroll
            for (int s = 0; s < 4; s++) {
                const int chunk = 4 * s + lqt;
                uint4 u;
                u.x = f2tf32(fcomp(stg[0], s));
                u.y = f2tf32(fcomp(stg[1], s));
                u.z = f2tf32(fcomp(stg[2], s));
                u.w = f2tf32(fcomp(stg[3], s));
                *(uint4*)(kb + ((chunk ^ r7) << 2)) = u;
            }
        } else {
            uint32_t* vb = Vt + buf * 2048;
            const int pos = (lrw & 3) * 8 + (lrw >> 2);
            const int pch = pos >> 2, pwd = pos & 3;
            #pragma unroll
            for (int i = 0; i < 4; i++) {
                #pragma unroll
                for (int j = 0; j < 4; j++) {
                    const int d = lqt * 16 + 4 * i + j;
                    vb[d * 32 + ((pch ^ (d & 7)) << 2) + pwd] = f2tf32(fcomp(stg[i], j));
                }
            }
        }
    };

    ldTile(0);
    stTile(0);
    __syncthreads();

    const int ntiles = q0 / 32 + 4;
    const int src0 = (lane & ~3) + (t4 >> 1);
    const int src2 = src0 + 2;
    const bool odd = (t4 & 1) != 0;

    for (int t = 0; t < ntiles; t++) {
        const int k0  = t * 32;
        const int buf = t & 1;
        if (t + 1 < ntiles) ldTile((t + 1) * 32);

        if (k0 <= wq + 15) {
            // ---- S = Q' K^T ----
            float s[4][4] = {};
            const uint32_t* Kb = Ks + buf * 2048;
            #pragma unroll
            for (int fi = 0; fi < 4; fi++) {
                const int ch = 4 * t4 + fi;
                #pragma unroll
                for (int tn = 0; tn < 4; tn++) {
                    const int rn = tn * 8 + gid;
                    uint4 kb = *(const uint4*)(Kb + rn * 64 + ((ch ^ gid) << 2));
                    uint32_t bf0[2] = {kb.x, kb.y};
                    uint32_t bf1[2] = {kb.z, kb.w};
                    mma_tf32(s[tn], qf[2 * fi], bf0);
                    mma_tf32(s[tn], qf[2 * fi + 1], bf1);
                }
            }
            // ---- causal mask ----
            if (k0 + 31 > wq) {
                #pragma unroll
                for (int tn = 0; tn < 4; tn++) {
                    const int c = k0 + tn * 8 + 2 * t4;
                    if (c     > qrow0)     s[tn][0] = -3.0e38f;
                    if (c + 1 > qrow0)     s[tn][1] = -3.0e38f;
                    if (c     > qrow0 + 8) s[tn][2] = -3.0e38f;
                    if (c + 1 > qrow0 + 8) s[tn][3] = -3.0e38f;
                }
            }
            // ---- register softmax ----
            float mx0 = s[0][0], mx1 = s[0][2];
            #pragma unroll
            for (int tn = 0; tn < 4; tn++) {
                mx0 = fmaxf(mx0, fmaxf(s[tn][0], s[tn][1]));
                mx1 = fmaxf(mx1, fmaxf(s[tn][2], s[tn][3]));
            }
            mx0 = fmaxf(mx0, __shfl_xor_sync(0xffffffffu, mx0, 1));
            mx0 = fmaxf(mx0, __shfl_xor_sync(0xffffffffu, mx0, 2));
            mx1 = fmaxf(mx1, __shfl_xor_sync(0xffffffffu, mx1, 1));
            mx1 = fmaxf(mx1, __shfl_xor_sync(0xffffffffu, mx1, 2));
            const float mn0 = fmaxf(mrow0, mx0);
            const float mn1 = fmaxf(mrow1, mx1);

            uint32_t pb[4][4];
            float ps0 = 0.0f, ps1 = 0.0f;
            #pragma unroll
            for (int tn = 0; tn < 4; tn++) {
                float p0 = __expf(s[tn][0] - mn0);
                float p1 = __expf(s[tn][1] - mn0);
                float p2 = __expf(s[tn][2] - mn1);
                float p3 = __expf(s[tn][3] - mn1);
                ps0 += p0 + p1;
                ps1 += p2 + p3;
                pb[tn][0] = f2tf32(p0);
                pb[tn][1] = f2tf32(p1);
                pb[tn][2] = f2tf32(p2);
                pb[tn][3] = f2tf32(p3);
            }
            ps0 += __shfl_xor_sync(0xffffffffu, ps0, 1);
            ps0 += __shfl_xor_sync(0xffffffffu, ps0, 2);
            ps1 += __shfl_xor_sync(0xffffffffu, ps1, 1);
            ps1 += __shfl_xor_sync(0xffffffffu, ps1, 2);

            const float al0 = __expf(mrow0 - mn0);
            const float al1 = __expf(mrow1 - mn1);
            lrow0 = lrow0 * al0 + ps0;
            lrow1 = lrow1 * al1 + ps1;
            mrow0 = mn0;
            mrow1 = mn1;
            #pragma unroll
            for (int nd = 0; nd < 8; nd++) {
                Oacc[nd][0] *= al0; Oacc[nd][1] *= al0;
                Oacc[nd][2] *= al1; Oacc[nd][3] *= al1;
            }

            // ---- P C-frag -> A-frag via quad shuffles ----
            uint32_t pa[4][4];
            #pragma unroll
            for (int kc = 0; kc < 4; kc++) {
                uint32_t s00 = __shfl_sync(0xffffffffu, pb[kc][0], src0);
                uint32_t s01 = __shfl_sync(0xffffffffu, pb[kc][1], src0);
                uint32_t s10 = __shfl_sync(0xffffffffu, pb[kc][2], src0);
                uint32_t s11 = __shfl_sync(0xffffffffu, pb[kc][3], src0);
                uint32_t s20 = __shfl_sync(0xffffffffu, pb[kc][0], src2);
                uint32_t s21 = __shfl_sync(0xffffffffu, pb[kc][1], src2);
                uint32_t s30 = __shfl_sync(0xffffffffu, pb[kc][2], src2);
                uint32_t s31 = __shfl_sync(0xffffffffu, pb[kc][3], src2);
                pa[kc][0] = odd ? s01 : s00;
                pa[kc][1] = odd ? s11 : s10;
                pa[kc][2] = odd ? s21 : s20;
                pa[kc][3] = odd ? s31 : s30;
            }

            // ---- O += P V ----
            const uint32_t* Vb = Vt + buf * 2048;
            #pragma unroll
            for (int fi = 0; fi < 2; fi++) {
                const int ch = 2 * t4 + fi;
                #pragma unroll
                for (int nd = 0; nd < 8; nd++) {
                    const int dn = nd * 8 + gid;
                    uint4 vv = *(const uint4*)(Vb + dn * 32 + ((ch ^ gid) << 2));
                    uint32_t bf0[2] = {vv.x, vv.y};
                    uint32_t bf1[2] = {vv.z, vv.w};
                    mma_tf32(Oacc[nd], pa[2 * fi], bf0);
                    mma_tf32(Oacc[nd], pa[2 * fi + 1], bf1);
                }
            }
        }

        if (t + 1 < ntiles) stTile(buf ^ 1);
        __syncthreads();
    }

    // ---- write normalized output to [B,L,D] ----
    const float inv0 = 1.0f / lrow0;
    const float inv1 = 1.0f / lrow1;
    float* o0 = att + ((size_t)(b * Lc + qrow0))     * Dd + h * DK;
    float* o1 = att + ((size_t)(b * Lc + qrow0 + 8)) * Dd + h * DK;
    #pragma unroll
    for (int nd = 0; nd < 8; nd++) {
        const int cc = nd * 8 + 2 * t4;
        float2 v0, v1;
        v0.x = Oacc[nd][0] * inv0; v0.y = Oacc[nd][1] * inv0;
        v1.x = Oacc[nd][2] * inv1; v1.y = Oacc[nd][3] * inv1;
        *(float2*)(o0 + cc) = v0;
        *(float2*)(o1 + cc) = v1;
    }
}

// ---------------- launch ----------------
extern "C" void kernel_launch(void* const* d_in, const int* in_sizes, int n_in,
                              void* d_out, int out_size)
{
    const float* q    = (const float*)d_in[0];
    const float* k    = (const float*)d_in[1];
    const float* v    = (const float*)d_in[2];
    const float* wq_w = (const float*)d_in[3];
    const float* wq_b = (const float*)d_in[4];
    const float* wk_w = (const float*)d_in[5];
    const float* wk_b = (const float*)d_in[6];
    const float* wv_w = (const float*)d_in[7];
    const float* wv_b = (const float*)d_in[8];
    const float* wo_w = (const float*)d_in[9];
    const float* wo_b = (const float*)d_in[10];
    float* out = (float*)d_out;

    float *pQ, *pK, *pV, *pAtt;
    cudaGetSymbolAddress((void**)&pQ,   g_Q);
    cudaGetSymbolAddress((void**)&pK,   g_K);
    cudaGetSymbolAddress((void**)&pV,   g_V);
    cudaGetSymbolAddress((void**)&pAtt, g_att);

    cudaFuncSetAttribute(gemm_qkv_kernel, cudaFuncAttributeMaxDynamicSharedMemorySize, GEMM_SMEM_BYTES);
    cudaFuncSetAttribute(gemm_o_kernel,   cudaFuncAttributeMaxDynamicSharedMemorySize, GEMM_SMEM_BYTES);
    cudaFuncSetAttribute(attn_mma_kernel, cudaFuncAttributeMaxDynamicSharedMemorySize, ATTN_SMEM_BYTES);

    QKVArgs args;
    args.X[0] = q;    args.X[1] = k;    args.X[2] = v;
    args.W[0] = wq_w; args.W[1] = wk_w; args.W[2] = wv_w;
    args.bias[0] = wq_b; args.bias[1] = wk_b; args.bias[2] = wv_b;
    args.out[0] = pQ; args.out[1] = pK; args.out[2] = pV;

    dim3 gq(Dd / 128, Mtok / 256, 3);   // (8, 32, 3)
    gemm_qkv_kernel<<<gq, 256, GEMM_SMEM_BYTES>>>(args);

    dim3 ga(Lc / 128, Hh, Bc);          // (16, 16, 4)
    attn_mma_kernel<<<ga, 256, ATTN_SMEM_BYTES>>>(pQ, pK, pV, pAtt);

    dim3 gg(Dd / 128, Mtok / 256);      // (8, 32)
    gemm_o_kernel<<<gg, 256, GEMM_SMEM_BYTES>>>(pAtt, wo_w, wo_b, out);
}

// round 7
// speedup vs baseline: 4.3722x; 1.1449x over previous
#include <cuda_runtime.h>
#include <cuda_bf16.h>
#include <math.h>
#include <cstdint>

constexpr int Bc = 4;
constexpr int Lc = 2048;
constexpr int Dd = 1024;
constexpr int Hh = 16;
constexpr int DK = 64;
constexpr int Mtok = Bc * Lc;   // 8192

// ---------------- scratch ----------------
__device__ float g_Q[Bc * Hh * Lc * DK];   // [B,H,L,DK] (tf32 bits)
__device__ float g_K[Bc * Hh * Lc * DK];
__device__ float g_V[Bc * Hh * Lc * DK];
__device__ float g_att[Bc * Lc * Dd];      // [B,L,D]    (tf32 bits)
// tf32-converted inputs/weights
__device__ float g_qc[Mtok * Dd];
__device__ float g_kc[Mtok * Dd];
__device__ float g_vc[Mtok * Dd];
__device__ float g_wqc[Dd * Dd];
__device__ float g_wkc[Dd * Dd];
__device__ float g_wvc[Dd * Dd];
__device__ float g_woc[Dd * Dd];

// ---------------- helpers ----------------
__device__ __forceinline__ uint32_t f2tf32(float f) {
    uint32_t r;
    asm("cvt.rna.tf32.f32 %0, %1;" : "=r"(r) : "f"(f));
    return r;
}

__device__ __forceinline__ void mma_tf32(float* d, const uint32_t* a, const uint32_t* b) {
    asm volatile(
        "mma.sync.aligned.m16n8k8.row.col.f32.tf32.tf32.f32 "
        "{%0,%1,%2,%3}, {%4,%5,%6,%7}, {%8,%9}, {%0,%1,%2,%3};\n"
        : "+f"(d[0]), "+f"(d[1]), "+f"(d[2]), "+f"(d[3])
        : "r"(a[0]), "r"(a[1]), "r"(a[2]), "r"(a[3]), "r"(b[0]), "r"(b[1]));
}

__device__ __forceinline__ void ldsm4(uint32_t* r, uint32_t addr) {
    asm volatile("ldmatrix.sync.aligned.m8n8.x4.shared.b16 {%0,%1,%2,%3}, [%4];"
                 : "=r"(r[0]), "=r"(r[1]), "=r"(r[2]), "=r"(r[3]) : "r"(addr));
}

__device__ __forceinline__ uint32_t smem_u32(const void* p) {
    uint32_t a;
    asm("{ .reg .u64 t; cvta.to.shared.u64 t, %1; cvt.u32.u64 %0, t; }" : "=r"(a) : "l"(p));
    return a;
}

#define CP16(dst, src) \
    asm volatile("cp.async.cg.shared.global [%0], [%1], 16;" :: "r"(dst), "l"(src))
#define CP_COMMIT() asm volatile("cp.async.commit_group;")
#define CP_WAIT1()  asm volatile("cp.async.wait_group 1;")

__device__ __forceinline__ float fcomp(const float4& v, int j) {
    return (j == 0) ? v.x : (j == 1) ? v.y : (j == 2) ? v.z : v.w;
}

// ---------------- tf32 pre-convert ----------------
__global__ void __launch_bounds__(256) conv_tf32_kernel(const float4* __restrict__ src,
                                                        float4* __restrict__ dst, int n4)
{
    const int i = blockIdx.x * 256 + threadIdx.x;
    if (i < n4) {
        float4 v = src[i];
        uint4 u;
        u.x = f2tf32(v.x); u.y = f2tf32(v.y); u.z = f2tf32(v.z); u.w = f2tf32(v.w);
        ((uint4*)dst)[i] = u;
    }
}

// =====================================================================
// GEMM: cp.async 3-stage pipeline + ldmatrix, tf32-bit inputs.
// CTA 256x128, 8 warps (4m x 2n), warp 64x64, BK=32.
// smem per stage: A 256x32 words + B 128x32 words (row-major,
// 16B chunks, chunk ^= row&7 swizzle).
// mode 0: fp32 out[m*1024+n]; mode 1: tf32-bit out in [B,H,L,DK]
// =====================================================================
constexpr int AW = 256 * 32;            // words per A stage
constexpr int BW = 128 * 32;
constexpr int STAGE_W = AW + BW;        // 12288 words = 48 KB
constexpr int GEMM_SMEM_BYTES = 3 * STAGE_W * 4;  // 147456

__device__ __forceinline__ void gemm_core(const float* __restrict__ X,
                                          const float* __restrict__ W,
                                          const float* __restrict__ bias,
                                          float* __restrict__ out,
                                          int mode, int bx, int by,
                                          uint32_t sbase)
{
    const int tid  = threadIdx.x;
    const int w    = tid >> 5;
    const int lane = tid & 31;
    const int gid  = lane >> 2;
    const int t4   = lane & 3;

    const int m0 = by * 256;
    const int n0 = bx * 128;
    const int wm = (w >> 1) * 64;
    const int wn = (w & 1) * 64;

    const int lr = tid >> 3;   // 0..31
    const int ch = tid & 7;    // 16B chunk

    const int within = lane & 7;
    const int sel    = lane >> 3;

    float acc[4][8][4] = {};

    auto issue = [&](int stage, int kt) {
        const uint32_t ab = sbase + stage * (STAGE_W * 4);
        const uint32_t bb = ab + AW * 4;
        const float* ap = X + (size_t)(m0 + lr) * Dd + kt * 32 + ch * 4;
        #pragma unroll
        for (int i = 0; i < 8; i++) {
            const int row = lr + 32 * i;
            const uint32_t dst = ab + row * 128 + ((ch ^ (row & 7)) << 4);
            CP16(dst, ap + (size_t)(32 * i) * Dd);
        }
        const float* bp = W + (size_t)(n0 + lr) * Dd + kt * 32 + ch * 4;
        #pragma unroll
        for (int i = 0; i < 4; i++) {
            const int row = lr + 32 * i;
            const uint32_t dst = bb + row * 128 + ((ch ^ (row & 7)) << 4);
            CP16(dst, bp + (size_t)(32 * i) * Dd);
        }
        CP_COMMIT();
    };

    issue(0, 0);
    issue(1, 1);

    for (int kt = 0; kt < 32; kt++) {
        const int cs = kt % 3;
        CP_WAIT1();
        __syncthreads();
        if (kt < 30) issue((kt + 2) % 3, kt + 2);
        else         CP_COMMIT();   // keep group numbering uniform

        const uint32_t ab = sbase + cs * (STAGE_W * 4);
        const uint32_t bb = ab + AW * 4;

        #pragma unroll
        for (int g = 0; g < 4; g++) {
            uint32_t af[4][4];
            #pragma unroll
            for (int tm = 0; tm < 4; tm++) {
                const int row = wm + tm * 16 + ((sel & 1) << 3) + within;
                const int cc  = 2 * g + (sel >> 1);
                ldsm4(af[tm], ab + row * 128 + ((cc ^ (row & 7)) << 4));
            }
            uint32_t bf[4][4];
            #pragma unroll
            for (int np = 0; np < 4; np++) {
                const int row = wn + (2 * np + (sel >> 1)) * 8 + within;
                const int cc  = 2 * g + (sel & 1);
                ldsm4(bf[np], bb + row * 128 + ((cc ^ (row & 7)) << 4));
            }
            #pragma unroll
            for (int tm = 0; tm < 4; tm++)
                #pragma unroll
                for (int np = 0; np < 4; np++) {
                    mma_tf32(acc[tm][2 * np],     af[tm], &bf[np][0]);
                    mma_tf32(acc[tm][2 * np + 1], af[tm], &bf[np][2]);
                }
        }
    }

    // epilogue
    #pragma unroll
    for (int tm = 0; tm < 4; tm++) {
        const int r0 = m0 + wm + tm * 16 + gid;
        const int r1 = r0 + 8;
        #pragma unroll
        for (int tn = 0; tn < 8; tn++) {
            const int cc = n0 + wn + tn * 8 + t4 * 2;
            const float bv0 = __ldg(bias + cc);
            const float bv1 = __ldg(bias + cc + 1);
            float2 v0, v1;
            v0.x = acc[tm][tn][0] + bv0;  v0.y = acc[tm][tn][1] + bv1;
            v1.x = acc[tm][tn][2] + bv0;  v1.y = acc[tm][tn][3] + bv1;
            if (mode == 0) {
                *(float2*)(out + (size_t)r0 * Dd + cc) = v0;
                *(float2*)(out + (size_t)r1 * Dd + cc) = v1;
            } else {
                v0.x = __uint_as_float(f2tf32(v0.x));
                v0.y = __uint_as_float(f2tf32(v0.y));
                v1.x = __uint_as_float(f2tf32(v1.x));
                v1.y = __uint_as_float(f2tf32(v1.y));
                const int h = cc >> 6, dk = cc & 63;
                {
                    const int b = r0 >> 11, l = r0 & 2047;
                    *(float2*)(out + (((size_t)(b * Hh + h) * Lc + l) << 6) + dk) = v0;
                }
                {
                    const int b = r1 >> 11, l = r1 & 2047;
                    *(float2*)(out + (((size_t)(b * Hh + h) * Lc + l) << 6) + dk) = v1;
                }
            }
        }
    }
}

struct QKVArgs {
    const float* X[3];
    const float* W[3];
    const float* bias[3];
    float* out[3];
};

__global__ void __launch_bounds__(256) gemm_qkv_kernel(QKVArgs args)
{
    extern __shared__ uint32_t sg[];
    const int z = blockIdx.z;
    gemm_core(args.X[z], args.W[z], args.bias[z], args.out[z], 1,
              blockIdx.x, blockIdx.y, smem_u32(sg));
}

__global__ void __launch_bounds__(256) gemm_o_kernel(const float* __restrict__ X,
                                                     const float* __restrict__ W,
                                                     const float* __restrict__ bias,
                                                     float* __restrict__ out)
{
    extern __shared__ uint32_t sg[];
    gemm_core(X, W, bias, out, 0, blockIdx.x, blockIdx.y, smem_u32(sg));
}

// =====================================================================
// Causal flash attention (R6 structure), inputs are tf32 bits already.
// =====================================================================
constexpr int ATTN_SMEM_BYTES = (2 * 32 * 64 + 2 * 64 * 32) * 4;  // 32768

__global__ void __launch_bounds__(256, 2) attn_mma_kernel(const float* __restrict__ Qg,
                                                          const float* __restrict__ Kg,
                                                          const float* __restrict__ Vg,
                                                          float* __restrict__ att)
{
    extern __shared__ uint32_t sa[];
    uint32_t* Ks = sa;                 // [2][32*64]
    uint32_t* Vt = sa + 2 * 32 * 64;   // [2][64*32]

    const int tid  = threadIdx.x;
    const int w    = tid >> 5;
    const int lane = tid & 31;
    const int gid  = lane >> 2;
    const int t4   = lane & 3;

    const int qb = gridDim.x - 1 - blockIdx.x;   // LPT
    const int q0 = qb * 128;
    const int h  = blockIdx.y;
    const int b  = blockIdx.z;

    const int wq    = q0 + w * 16;
    const int qrow0 = wq + gid;

    const size_t base = (size_t)(b * Hh + h) * Lc * DK;
    const float* Qbh = Qg + base;
    const float* Kbh = Kg + base;
    const float* Vbh = Vg + base;

    // ---- Q fragments (bits are tf32; *0.125 is exact) ----
    uint32_t qf[8][4];
    {
        const float* qp0 = Qbh + (size_t)qrow0 * DK;
        const float* qp1 = qp0 + 8 * DK;
        #pragma unroll
        for (int kc = 0; kc < 8; kc++) {
            const int c0 = kc * 8 + t4, c1 = c0 + 4;
            qf[kc][0] = __float_as_uint(__ldg(qp0 + c0) * 0.125f);
            qf[kc][1] = __float_as_uint(__ldg(qp1 + c0) * 0.125f);
            qf[kc][2] = __float_as_uint(__ldg(qp0 + c1) * 0.125f);
            qf[kc][3] = __float_as_uint(__ldg(qp1 + c1) * 0.125f);
        }
    }

    float Oacc[8][4] = {};
    float mrow0 = -3.0e38f, mrow1 = -3.0e38f;
    float lrow0 = 0.0f,     lrow1 = 0.0f;

    const bool isK = tid < 128;
    const int  lrw = (tid & 127) >> 2;
    const int  lqt = tid & 3;
    const float* lp = (isK ? Kbh : Vbh) + (size_t)lrw * DK + lqt * 16;

    float4 stg[4];
    auto ldTile = [&](int k0) {
        const float* p = lp + (size_t)k0 * DK;
        #pragma unroll
        for (int i = 0; i < 4; i++) stg[i] = *(const float4*)(p + 4 * i);
    };
    auto stTile = [&](int buf) {
        if (isK) {
            uint32_t* kb = Ks + buf * 2048 + lrw * 64;
            const int r7 = lrw & 7;
            #pragma unroll
            for (int s = 0; s < 4; s++) {
                const int chunk = 4 * s + lqt;
                uint4 u;
                u.x = __float_as_uint(fcomp(stg[0], s));
                u.y = __float_as_uint(fcomp(stg[1], s));
                u.z = __float_as_uint(fcomp(stg[2], s));
                u.w = __float_as_uint(fcomp(stg[3], s));
                *(uint4*)(kb + ((chunk ^ r7) << 2)) = u;
            }
        } else {
            uint32_t* vb = Vt + buf * 2048;
            const int pos = (lrw & 3) * 8 + (lrw >> 2);
            const int pch = pos >> 2, pwd = pos & 3;
            #pragma unroll
            for (int i = 0; i < 4; i++) {
                #pragma unroll
                for (int j = 0; j < 4; j++) {
                    const int d = lqt * 16 + 4 * i + j;
                    vb[d * 32 + ((pch ^ (d & 7)) << 2) + pwd] = __float_as_uint(fcomp(stg[i], j));
                }
            }
        }
    };

    ldTile(0);
    stTile(0);
    __syncthreads();

    const int ntiles = q0 / 32 + 4;
    const int src0 = (lane & ~3) + (t4 >> 1);
    const int src2 = src0 + 2;
    const bool odd = (t4 & 1) != 0;

    for (int t = 0; t < ntiles; t++) {
        const int k0  = t * 32;
        const int buf = t & 1;
        if (t + 1 < ntiles) ldTile((t + 1) * 32);

        if (k0 <= wq + 15) {
            float s[4][4] = {};
            const uint32_t* Kb = Ks + buf * 2048;
            #pragma unroll
            for (int fi = 0; fi < 4; fi++) {
                const int cc = 4 * t4 + fi;
                #pragma unroll
                for (int tn = 0; tn < 4; tn++) {
                    const int rn = tn * 8 + gid;
                    uint4 kb = *(const uint4*)(Kb + rn * 64 + ((cc ^ gid) << 2));
                    uint32_t bf0[2] = {kb.x, kb.y};
                    uint32_t bf1[2] = {kb.z, kb.w};
                    mma_tf32(s[tn], qf[2 * fi], bf0);
                    mma_tf32(s[tn], qf[2 * fi + 1], bf1);
                }
            }
            if (k0 + 31 > wq) {
                #pragma unroll
                for (int tn = 0; tn < 4; tn++) {
                    const int c = k0 + tn * 8 + 2 * t4;
                    if (c     > qrow0)     s[tn][0] = -3.0e38f;
                    if (c + 1 > qrow0)     s[tn][1] = -3.0e38f;
                    if (c     > qrow0 + 8) s[tn][2] = -3.0e38f;
                    if (c + 1 > qrow0 + 8) s[tn][3] = -3.0e38f;
                }
            }
            float mx0 = s[0][0], mx1 = s[0][2];
            #pragma unroll
            for (int tn = 0; tn < 4; tn++) {
                mx0 = fmaxf(mx0, fmaxf(s[tn][0], s[tn][1]));
                mx1 = fmaxf(mx1, fmaxf(s[tn][2], s[tn][3]));
            }
            mx0 = fmaxf(mx0, __shfl_xor_sync(0xffffffffu, mx0, 1));
            mx0 = fmaxf(mx0, __shfl_xor_sync(0xffffffffu, mx0, 2));
            mx1 = fmaxf(mx1, __shfl_xor_sync(0xffffffffu, mx1, 1));
            mx1 = fmaxf(mx1, __shfl_xor_sync(0xffffffffu, mx1, 2));
            const float mn0 = fmaxf(mrow0, mx0);
            const float mn1 = fmaxf(mrow1, mx1);

            uint32_t pb[4][4];
            float ps0 = 0.0f, ps1 = 0.0f;
            #pragma unroll
            for (int tn = 0; tn < 4; tn++) {
                float p0 = __expf(s[tn][0] - mn0);
                float p1 = __expf(s[tn][1] - mn0);
                float p2 = __expf(s[tn][2] - mn1);
                float p3 = __expf(s[tn][3] - mn1);
                ps0 += p0 + p1;
                ps1 += p2 + p3;
                pb[tn][0] = f2tf32(p0);
                pb[tn][1] = f2tf32(p1);
                pb[tn][2] = f2tf32(p2);
                pb[tn][3] = f2tf32(p3);
            }
            ps0 += __shfl_xor_sync(0xffffffffu, ps0, 1);
            ps0 += __shfl_xor_sync(0xffffffffu, ps0, 2);
            ps1 += __shfl_xor_sync(0xffffffffu, ps1, 1);
            ps1 += __shfl_xor_sync(0xffffffffu, ps1, 2);

            const float al0 = __expf(mrow0 - mn0);
            const float al1 = __expf(mrow1 - mn1);
            lrow0 = lrow0 * al0 + ps0;
            lrow1 = lrow1 * al1 + ps1;
            mrow0 = mn0;
            mrow1 = mn1;
            #pragma unroll
            for (int nd = 0; nd < 8; nd++) {
                Oacc[nd][0] *= al0; Oacc[nd][1] *= al0;
                Oacc[nd][2] *= al1; Oacc[nd][3] *= al1;
            }

            uint32_t pa[4][4];
            #pragma unroll
            for (int kc = 0; kc < 4; kc++) {
                uint32_t s00 = __shfl_sync(0xffffffffu, pb[kc][0], src0);
                uint32_t s01 = __shfl_sync(0xffffffffu, pb[kc][1], src0);
                uint32_t s10 = __shfl_sync(0xffffffffu, pb[kc][2], src0);
                uint32_t s11 = __shfl_sync(0xffffffffu, pb[kc][3], src0);
                uint32_t s20 = __shfl_sync(0xffffffffu, pb[kc][0], src2);
                uint32_t s21 = __shfl_sync(0xffffffffu, pb[kc][1], src2);
                uint32_t s30 = __shfl_sync(0xffffffffu, pb[kc][2], src2);
                uint32_t s31 = __shfl_sync(0xffffffffu, pb[kc][3], src2);
                pa[kc][0] = odd ? s01 : s00;
                pa[kc][1] = odd ? s11 : s10;
                pa[kc][2] = odd ? s21 : s20;
                pa[kc][3] = odd ? s31 : s30;
            }

            const uint32_t* Vb = Vt + buf * 2048;
            #pragma unroll
            for (int fi = 0; fi < 2; fi++) {
                const int cc = 2 * t4 + fi;
                #pragma unroll
                for (int nd = 0; nd < 8; nd++) {
                    const int dn = nd * 8 + gid;
                    uint4 vv = *(const uint4*)(Vb + dn * 32 + ((cc ^ gid) << 2));
                    uint32_t bf0[2] = {vv.x, vv.y};
                    uint32_t bf1[2] = {vv.z, vv.w};
                    mma_tf32(Oacc[nd], pa[2 * fi], bf0);
                    mma_tf32(Oacc[nd], pa[2 * fi + 1], bf1);
                }
            }
        }

        if (t + 1 < ntiles) stTile(buf ^ 1);
        __syncthreads();
    }

    // ---- write normalized output (tf32 bits) to [B,L,D] ----
    const float inv0 = 1.0f / lrow0;
    const float inv1 = 1.0f / lrow1;
    float* o0 = att + ((size_t)(b * Lc + qrow0))     * Dd + h * DK;
    float* o1 = att + ((size_t)(b * Lc + qrow0 + 8)) * Dd + h * DK;
    #pragma unroll
    for (int nd = 0; nd < 8; nd++) {
        const int cc = nd * 8 + 2 * t4;
        float2 v0, v1;
        v0.x = __uint_as_float(f2tf32(Oacc[nd][0] * inv0));
        v0.y = __uint_as_float(f2tf32(Oacc[nd][1] * inv0));
        v1.x = __uint_as_float(f2tf32(Oacc[nd][2] * inv1));
        v1.y = __uint_as_float(f2tf32(Oacc[nd][3] * inv1));
        *(float2*)(o0 + cc) = v0;
        *(float2*)(o1 + cc) = v1;
    }
}

// ---------------- launch ----------------
extern "C" void kernel_launch(void* const* d_in, const int* in_sizes, int n_in,
                              void* d_out, int out_size)
{
    const float* q    = (const float*)d_in[0];
    const float* k    = (const float*)d_in[1];
    const float* v    = (const float*)d_in[2];
    const float* wq_w = (const float*)d_in[3];
    const float* wq_b = (const float*)d_in[4];
    const float* wk_w = (const float*)d_in[5];
    const float* wk_b = (const float*)d_in[6];
    const float* wv_w = (const float*)d_in[7];
    const float* wv_b = (const float*)d_in[8];
    const float* wo_w = (const float*)d_in[9];
    const float* wo_b = (const float*)d_in[10];
    float* out = (float*)d_out;

    float *pQ, *pK, *pV, *pAtt;
    float *pqc, *pkc, *pvc, *pwq, *pwk, *pwv, *pwo;
    cudaGetSymbolAddress((void**)&pQ,   g_Q);
    cudaGetSymbolAddress((void**)&pK,   g_K);
    cudaGetSymbolAddress((void**)&pV,   g_V);
    cudaGetSymbolAddress((void**)&pAtt, g_att);
    cudaGetSymbolAddress((void**)&pqc,  g_qc);
    cudaGetSymbolAddress((void**)&pkc,  g_kc);
    cudaGetSymbolAddress((void**)&pvc,  g_vc);
    cudaGetSymbolAddress((void**)&pwq,  g_wqc);
    cudaGetSymbolAddress((void**)&pwk,  g_wkc);
    cudaGetSymbolAddress((void**)&pwv,  g_wvc);
    cudaGetSymbolAddress((void**)&pwo,  g_woc);

    cudaFuncSetAttribute(gemm_qkv_kernel, cudaFuncAttributeMaxDynamicSharedMemorySize, GEMM_SMEM_BYTES);
    cudaFuncSetAttribute(gemm_o_kernel,   cudaFuncAttributeMaxDynamicSharedMemorySize, GEMM_SMEM_BYTES);
    cudaFuncSetAttribute(attn_mma_kernel, cudaFuncAttributeMaxDynamicSharedMemorySize, ATTN_SMEM_BYTES);

    // ---- pre-convert to tf32 bits ----
    const int nBig4   = Mtok * Dd / 4;   // 2M float4
    const int nSmall4 = Dd * Dd / 4;     // 256K float4
    conv_tf32_kernel<<<(nBig4 + 255) / 256, 256>>>((const float4*)q, (float4*)pqc, nBig4);
    conv_tf32_kernel<<<(nBig4 + 255) / 256, 256>>>((const float4*)k, (float4*)pkc, nBig4);
    conv_tf32_kernel<<<(nBig4 + 255) / 256, 256>>>((const float4*)v, (float4*)pvc, nBig4);
    conv_tf32_kernel<<<(nSmall4 + 255) / 256, 256>>>((const float4*)wq_w, (float4*)pwq, nSmall4);
    conv_tf32_kernel<<<(nSmall4 + 255) / 256, 256>>>((const float4*)wk_w, (float4*)pwk, nSmall4);
    conv_tf32_kernel<<<(nSmall4 + 255) / 256, 256>>>((const float4*)wv_w, (float4*)pwv, nSmall4);
    conv_tf32_kernel<<<(nSmall4 + 255) / 256, 256>>>((const float4*)wo_w, (float4*)pwo, nSmall4);

    QKVArgs args;
    args.X[0] = pqc;  args.X[1] = pkc;  args.X[2] = pvc;
    args.W[0] = pwq;  args.W[1] = pwk;  args.W[2] = pwv;
    args.bias[0] = wq_b; args.bias[1] = wk_b; args.bias[2] = wv_b;
    args.out[0] = pQ; args.out[1] = pK; args.out[2] = pV;

    dim3 gq(Dd / 128, Mtok / 256, 3);   // (8, 32, 3)
    gemm_qkv_kernel<<<gq, 256, GEMM_SMEM_BYTES>>>(args);

    dim3 ga(Lc / 128, Hh, Bc);          // (16, 16, 4)
    attn_mma_kernel<<<ga, 256, ATTN_SMEM_BYTES>>>(pQ, pK, pV, pAtt);

    dim3 gg(Dd / 128, Mtok / 256);      // (8, 32)
    gemm_o_kernel<<<gg, 256, GEMM_SMEM_BYTES>>>(pAtt, pwo, wo_b, out);
}

// round 8
// speedup vs baseline: 5.5026x; 1.2585x over previous
#include <cuda_runtime.h>
#include <cuda_bf16.h>
#include <math.h>
#include <cstdint>

constexpr int Bc = 4;
constexpr int Lc = 2048;
constexpr int Dd = 1024;
constexpr int Hh = 16;
constexpr int DK = 64;
constexpr int Mtok = Bc * Lc;   // 8192

// ---------------- scratch ----------------
__device__ float g_Q[Bc * Hh * Lc * DK];   // [B,H,L,DK] (tf32 bits)
__device__ float g_K[Bc * Hh * Lc * DK];
__device__ float g_V[Bc * Hh * Lc * DK];
__device__ float g_Vt[Bc * Hh * DK * Lc];  // [B,H,DK,L] (tf32 bits)
__device__ float g_att[Bc * Lc * Dd];      // [B,L,D]    (tf32 bits)
__device__ float g_conv[7340032 * 4];      // concatenated tf32 copies

// segment offsets in float4 units
constexpr int SEG_Q  = 0;
constexpr int SEG_K  = 2097152;
constexpr int SEG_V  = 4194304;
constexpr int SEG_WQ = 6291456;
constexpr int SEG_WK = 6553600;
constexpr int SEG_WV = 6815744;
constexpr int SEG_WO = 7077888;
constexpr int SEG_TOT = 7340032;

// ---------------- helpers ----------------
__device__ __forceinline__ uint32_t f2tf32(float f) {
    uint32_t r;
    asm("cvt.rna.tf32.f32 %0, %1;" : "=r"(r) : "f"(f));
    return r;
}

__device__ __forceinline__ void mma_tf32(float* d, const uint32_t* a, const uint32_t* b) {
    asm volatile(
        "mma.sync.aligned.m16n8k8.row.col.f32.tf32.tf32.f32 "
        "{%0,%1,%2,%3}, {%4,%5,%6,%7}, {%8,%9}, {%0,%1,%2,%3};\n"
        : "+f"(d[0]), "+f"(d[1]), "+f"(d[2]), "+f"(d[3])
        : "r"(a[0]), "r"(a[1]), "r"(a[2]), "r"(a[3]), "r"(b[0]), "r"(b[1]));
}

__device__ __forceinline__ void ldsm4(uint32_t* r, uint32_t addr) {
    asm volatile("ldmatrix.sync.aligned.m8n8.x4.shared.b16 {%0,%1,%2,%3}, [%4];"
                 : "=r"(r[0]), "=r"(r[1]), "=r"(r[2]), "=r"(r[3]) : "r"(addr));
}

__device__ __forceinline__ uint32_t smem_u32(const void* p) {
    uint32_t a;
    asm("{ .reg .u64 t; cvta.to.shared.u64 t, %1; cvt.u32.u64 %0, t; }" : "=r"(a) : "l"(p));
    return a;
}

#define CP16(dst, src) \
    asm volatile("cp.async.cg.shared.global [%0], [%1], 16;" :: "r"(dst), "l"(src))
#define CP_COMMIT() asm volatile("cp.async.commit_group;")
#define CP_WAIT1()  asm volatile("cp.async.wait_group 1;")

// ---------------- fused tf32 pre-convert (all 7 tensors) ----------------
struct ConvArgs {
    const float4* s0; const float4* s1; const float4* s2;
    const float4* s3; const float4* s4; const float4* s5; const float4* s6;
    float4* dst;
};

__global__ void __launch_bounds__(256) conv_all_kernel(ConvArgs a)
{
    const int g = blockIdx.x * 256 + threadIdx.x;   // 0 .. 1,835,007
    constexpr int NT = SEG_TOT / 4;                  // 1,835,008
    #pragma unroll
    for (int p = 0; p < 4; p++) {
        const int idx = g + p * NT;
        float4 v;
        if (idx < SEG_WQ) {
            const int seg = idx >> 21;               // /2097152
            const int off = idx & 2097151;
            v = (seg == 0) ? a.s0[off] : (seg == 1) ? a.s1[off] : a.s2[off];
        } else {
            const int r = idx - SEG_WQ;
            const int seg = r >> 18;                 // /262144
            const int off = r & 262143;
            v = (seg == 0) ? a.s3[off] : (seg == 1) ? a.s4[off]
              : (seg == 2) ? a.s5[off] : a.s6[off];
        }
        uint4 u;
        u.x = f2tf32(v.x); u.y = f2tf32(v.y); u.z = f2tf32(v.z); u.w = f2tf32(v.w);
        ((uint4*)a.dst)[idx] = u;
    }
}

// ---------------- V transpose: [B,H,L,DK] -> [B,H,DK,L] ----------------
__global__ void __launch_bounds__(256) vtrans_kernel(const float* __restrict__ V,
                                                     float* __restrict__ Vt)
{
    __shared__ float sm[32][33];
    const int tx = threadIdx.x & 31;
    const int ty = threadIdx.x >> 5;   // 0..7
    const int l0 = blockIdx.x * 32;
    const int d0 = blockIdx.y * 32;
    const int bh = blockIdx.z;
    const float* src = V + (size_t)bh * Lc * DK;
    float* dst = Vt + (size_t)bh * DK * Lc;
    #pragma unroll
    for (int j = 0; j < 4; j++)
        sm[ty + 8 * j][tx] = src[(size_t)(l0 + ty + 8 * j) * DK + d0 + tx];
    __syncthreads();
    #pragma unroll
    for (int j = 0; j < 4; j++)
        dst[(size_t)(d0 + ty + 8 * j) * Lc + l0 + tx] = sm[tx][ty + 8 * j];
}

// =====================================================================
// GEMM: cp.async 3-stage pipeline + ldmatrix, tf32-bit inputs. (R7)
// CTA 256x128, 8 warps (4m x 2n), warp 64x64, BK=32.
// =====================================================================
constexpr int AW = 256 * 32;
constexpr int BW = 128 * 32;
constexpr int STAGE_W = AW + BW;
constexpr int GEMM_SMEM_BYTES = 3 * STAGE_W * 4;  // 147456

__device__ __forceinline__ void gemm_core(const float* __restrict__ X,
                                          const float* __restrict__ W,
                                          const float* __restrict__ bias,
                                          float* __restrict__ out,
                                          int mode, int bx, int by,
                                          uint32_t sbase)
{
    const int tid  = threadIdx.x;
    const int w    = tid >> 5;
    const int lane = tid & 31;
    const int gid  = lane >> 2;
    const int t4   = lane & 3;

    const int m0 = by * 256;
    const int n0 = bx * 128;
    const int wm = (w >> 1) * 64;
    const int wn = (w & 1) * 64;

    const int lr = tid >> 3;
    const int ch = tid & 7;

    const int within = lane & 7;
    const int sel    = lane >> 3;

    float acc[4][8][4] = {};

    auto issue = [&](int stage, int kt) {
        const uint32_t ab = sbase + stage * (STAGE_W * 4);
        const uint32_t bb = ab + AW * 4;
        const float* ap = X + (size_t)(m0 + lr) * Dd + kt * 32 + ch * 4;
        #pragma unroll
        for (int i = 0; i < 8; i++) {
            const int row = lr + 32 * i;
            const uint32_t dst = ab + row * 128 + ((ch ^ (row & 7)) << 4);
            CP16(dst, ap + (size_t)(32 * i) * Dd);
        }
        const float* bp = W + (size_t)(n0 + lr) * Dd + kt * 32 + ch * 4;
        #pragma unroll
        for (int i = 0; i < 4; i++) {
            const int row = lr + 32 * i;
            const uint32_t dst = bb + row * 128 + ((ch ^ (row & 7)) << 4);
            CP16(dst, bp + (size_t)(32 * i) * Dd);
        }
        CP_COMMIT();
    };

    issue(0, 0);
    issue(1, 1);

    for (int kt = 0; kt < 32; kt++) {
        const int cs = kt % 3;
        CP_WAIT1();
        __syncthreads();
        if (kt < 30) issue((kt + 2) % 3, kt + 2);
        else         CP_COMMIT();

        const uint32_t ab = sbase + cs * (STAGE_W * 4);
        const uint32_t bb = ab + AW * 4;

        #pragma unroll
        for (int g = 0; g < 4; g++) {
            uint32_t af[4][4];
            #pragma unroll
            for (int tm = 0; tm < 4; tm++) {
                const int row = wm + tm * 16 + ((sel & 1) << 3) + within;
                const int cc  = 2 * g + (sel >> 1);
                ldsm4(af[tm], ab + row * 128 + ((cc ^ (row & 7)) << 4));
            }
            uint32_t bf[4][4];
            #pragma unroll
            for (int np = 0; np < 4; np++) {
                const int row = wn + (2 * np + (sel >> 1)) * 8 + within;
                const int cc  = 2 * g + (sel & 1);
                ldsm4(bf[np], bb + row * 128 + ((cc ^ (row & 7)) << 4));
            }
            #pragma unroll
            for (int tm = 0; tm < 4; tm++)
                #pragma unroll
                for (int np = 0; np < 4; np++) {
                    mma_tf32(acc[tm][2 * np],     af[tm], &bf[np][0]);
                    mma_tf32(acc[tm][2 * np + 1], af[tm], &bf[np][2]);
                }
        }
    }

    #pragma unroll
    for (int tm = 0; tm < 4; tm++) {
        const int r0 = m0 + wm + tm * 16 + gid;
        const int r1 = r0 + 8;
        #pragma unroll
        for (int tn = 0; tn < 8; tn++) {
            const int cc = n0 + wn + tn * 8 + t4 * 2;
            const float bv0 = __ldg(bias + cc);
            const float bv1 = __ldg(bias + cc + 1);
            float2 v0, v1;
            v0.x = acc[tm][tn][0] + bv0;  v0.y = acc[tm][tn][1] + bv1;
            v1.x = acc[tm][tn][2] + bv0;  v1.y = acc[tm][tn][3] + bv1;
            if (mode == 0) {
                *(float2*)(out + (size_t)r0 * Dd + cc) = v0;
                *(float2*)(out + (size_t)r1 * Dd + cc) = v1;
            } else {
                v0.x = __uint_as_float(f2tf32(v0.x));
                v0.y = __uint_as_float(f2tf32(v0.y));
                v1.x = __uint_as_float(f2tf32(v1.x));
                v1.y = __uint_as_float(f2tf32(v1.y));
                const int h = cc >> 6, dk = cc & 63;
                {
                    const int b = r0 >> 11, l = r0 & 2047;
                    *(float2*)(out + (((size_t)(b * Hh + h) * Lc + l) << 6) + dk) = v0;
                }
                {
                    const int b = r1 >> 11, l = r1 & 2047;
                    *(float2*)(out + (((size_t)(b * Hh + h) * Lc + l) << 6) + dk) = v1;
                }
            }
        }
    }
}

struct QKVArgs {
    const float* X[3];
    const float* W[3];
    const float* bias[3];
    float* out[3];
};

__global__ void __launch_bounds__(256) gemm_qkv_kernel(QKVArgs args)
{
    extern __shared__ uint32_t sg[];
    const int z = blockIdx.z;
    gemm_core(args.X[z], args.W[z], args.bias[z], args.out[z], 1,
              blockIdx.x, blockIdx.y, smem_u32(sg));
}

__global__ void __launch_bounds__(256) gemm_o_kernel(const float* __restrict__ X,
                                                     const float* __restrict__ W,
                                                     const float* __restrict__ bias,
                                                     float* __restrict__ out)
{
    extern __shared__ uint32_t sg[];
    gemm_core(X, W, bias, out, 0, blockIdx.x, blockIdx.y, smem_u32(sg));
}

// =====================================================================
// Causal flash attention: cp.async 3-stage + ldmatrix + register softmax.
// CTA: 128 q-rows, 8 warps; warp = 16 q x 32 keys. V pre-transposed.
// Stage: K 32x64 words (row=key) + Vt 64x32 words (row=d), chunk^row&7.
// =====================================================================
constexpr int ATT_KW = 32 * 64;
constexpr int ATT_VW = 64 * 32;
constexpr int ATT_STAGE_W = ATT_KW + ATT_VW;       // 4096 words
constexpr int ATTN_SMEM_BYTES = 3 * ATT_STAGE_W * 4;  // 49152

__global__ void __launch_bounds__(256, 2) attn_mma_kernel(const float* __restrict__ Qg,
                                                          const float* __restrict__ Kg,
                                                          const float* __restrict__ Vtg,
                                                          float* __restrict__ att)
{
    extern __shared__ uint32_t sa[];
    const uint32_t sb = smem_u32(sa);

    const int tid  = threadIdx.x;
    const int w    = tid >> 5;
    const int lane = tid & 31;
    const int gid  = lane >> 2;
    const int t4   = lane & 3;
    const int within = lane & 7;
    const int sel    = lane >> 3;

    const int qb = gridDim.x - 1 - blockIdx.x;   // LPT
    const int q0 = qb * 128;
    const int h  = blockIdx.y;
    const int b  = blockIdx.z;

    const int wq    = q0 + w * 16;
    const int qrow0 = wq + gid;

    const size_t base = (size_t)(b * Hh + h) * Lc * DK;
    const float* Qbh  = Qg + base;
    const float* Kbh  = Kg + base;
    const float* Vtbh = Vtg + base;   // [DK][L]

    // ---- Q fragments (tf32 bits; *0.125 exact) ----
    uint32_t qf[8][4];
    {
        const float* qp0 = Qbh + (size_t)qrow0 * DK;
        const float* qp1 = qp0 + 8 * DK;
        #pragma unroll
        for (int kc = 0; kc < 8; kc++) {
            const int c0 = kc * 8 + t4, c1 = c0 + 4;
            qf[kc][0] = __float_as_uint(__ldg(qp0 + c0) * 0.125f);
            qf[kc][1] = __float_as_uint(__ldg(qp1 + c0) * 0.125f);
            qf[kc][2] = __float_as_uint(__ldg(qp0 + c1) * 0.125f);
            qf[kc][3] = __float_as_uint(__ldg(qp1 + c1) * 0.125f);
        }
    }

    float Oacc[8][4] = {};
    float mrow0 = -3.0e38f, mrow1 = -3.0e38f;
    float lrow0 = 0.0f,     lrow1 = 0.0f;

    // ---- cp.async tile issue: K 512 chunks + Vt 512 chunks, 4/thread ----
    auto issueKV = [&](int stage, int k0) {
        const uint32_t kb = sb + stage * (ATT_STAGE_W * 4);
        const uint32_t vb = kb + ATT_KW * 4;
        #pragma unroll
        for (int i = 0; i < 2; i++) {
            const int idx = tid * 2 + i;
            {   // K: row=key (16 chunks/row)
                const int row = idx >> 4, c = idx & 15;
                CP16(kb + row * 256 + ((c ^ (row & 7)) << 4),
                     Kbh + (size_t)(k0 + row) * DK + c * 4);
            }
            {   // Vt: row=d (8 chunks/row)
                const int row = idx >> 3, c = idx & 7;
                CP16(vb + row * 128 + ((c ^ (row & 7)) << 4),
                     Vtbh + (size_t)row * Lc + k0 + c * 4);
            }
        }
        CP_COMMIT();
    };

    const int ntiles = q0 / 32 + 4;
    issueKV(0, 0);
    issueKV(1, 32);

    const int src0 = (lane & ~3) + (t4 >> 1);
    const int src2 = src0 + 2;
    const bool odd = (t4 & 1) != 0;

    for (int t = 0; t < ntiles; t++) {
        const int k0 = t * 32;
        const int cs = t % 3;
        CP_WAIT1();
        __syncthreads();
        if (t + 2 < ntiles) issueKV((t + 2) % 3, (t + 2) * 32);
        else                CP_COMMIT();

        if (k0 <= wq + 15) {
            const uint32_t kst = sb + cs * (ATT_STAGE_W * 4);
            const uint32_t vst = kst + ATT_KW * 4;

            // ---- S = Q' K^T via ldmatrix B-frags ----
            float s[4][4] = {};
            #pragma unroll
            for (int st8 = 0; st8 < 8; st8++) {
                uint32_t bf[2][4];
                #pragma unroll
                for (int np = 0; np < 2; np++) {
                    const int row = (2 * np + (sel >> 1)) * 8 + within;
                    const int cc  = 2 * st8 + (sel & 1);
                    ldsm4(bf[np], kst + row * 256 + ((cc ^ (row & 7)) << 4));
                }
                mma_tf32(s[0], qf[st8], &bf[0][0]);
                mma_tf32(s[1], qf[st8], &bf[0][2]);
                mma_tf32(s[2], qf[st8], &bf[1][0]);
                mma_tf32(s[3], qf[st8], &bf[1][2]);
            }
            // ---- causal mask ----
            if (k0 + 31 > wq) {
                #pragma unroll
                for (int tn = 0; tn < 4; tn++) {
                    const int c = k0 + tn * 8 + 2 * t4;
                    if (c     > qrow0)     s[tn][0] = -3.0e38f;
                    if (c + 1 > qrow0)     s[tn][1] = -3.0e38f;
                    if (c     > qrow0 + 8) s[tn][2] = -3.0e38f;
                    if (c + 1 > qrow0 + 8) s[tn][3] = -3.0e38f;
                }
            }
            // ---- register softmax ----
            float mx0 = s[0][0], mx1 = s[0][2];
            #pragma unroll
            for (int tn = 0; tn < 4; tn++) {
                mx0 = fmaxf(mx0, fmaxf(s[tn][0], s[tn][1]));
                mx1 = fmaxf(mx1, fmaxf(s[tn][2], s[tn][3]));
            }
            mx0 = fmaxf(mx0, __shfl_xor_sync(0xffffffffu, mx0, 1));
            mx0 = fmaxf(mx0, __shfl_xor_sync(0xffffffffu, mx0, 2));
            mx1 = fmaxf(mx1, __shfl_xor_sync(0xffffffffu, mx1, 1));
            mx1 = fmaxf(mx1, __shfl_xor_sync(0xffffffffu, mx1, 2));
            const float mn0 = fmaxf(mrow0, mx0);
            const float mn1 = fmaxf(mrow1, mx1);

            uint32_t pb[4][4];
            float ps0 = 0.0f, ps1 = 0.0f;
            #pragma unroll
            for (int tn = 0; tn < 4; tn++) {
                float p0 = __expf(s[tn][0] - mn0);
                float p1 = __expf(s[tn][1] - mn0);
                float p2 = __expf(s[tn][2] - mn1);
                float p3 = __expf(s[tn][3] - mn1);
                ps0 += p0 + p1;
                ps1 += p2 + p3;
                pb[tn][0] = f2tf32(p0);
                pb[tn][1] = f2tf32(p1);
                pb[tn][2] = f2tf32(p2);
                pb[tn][3] = f2tf32(p3);
            }
            ps0 += __shfl_xor_sync(0xffffffffu, ps0, 1);
            ps0 += __shfl_xor_sync(0xffffffffu, ps0, 2);
            ps1 += __shfl_xor_sync(0xffffffffu, ps1, 1);
            ps1 += __shfl_xor_sync(0xffffffffu, ps1, 2);

            const float al0 = __expf(mrow0 - mn0);
            const float al1 = __expf(mrow1 - mn1);
            lrow0 = lrow0 * al0 + ps0;
            lrow1 = lrow1 * al1 + ps1;
            mrow0 = mn0;
            mrow1 = mn1;
            #pragma unroll
            for (int nd = 0; nd < 8; nd++) {
                Oacc[nd][0] *= al0; Oacc[nd][1] *= al0;
                Oacc[nd][2] *= al1; Oacc[nd][3] *= al1;
            }

            // ---- P C-frag -> A-frag via quad shuffles ----
            uint32_t pa[4][4];
            #pragma unroll
            for (int kc = 0; kc < 4; kc++) {
                uint32_t s00 = __shfl_sync(0xffffffffu, pb[kc][0], src0);
                uint32_t s01 = __shfl_sync(0xffffffffu, pb[kc][1], src0);
                uint32_t s10 = __shfl_sync(0xffffffffu, pb[kc][2], src0);
                uint32_t s11 = __shfl_sync(0xffffffffu, pb[kc][3], src0);
                uint32_t s20 = __shfl_sync(0xffffffffu, pb[kc][0], src2);
                uint32_t s21 = __shfl_sync(0xffffffffu, pb[kc][1], src2);
                uint32_t s30 = __shfl_sync(0xffffffffu, pb[kc][2], src2);
                uint32_t s31 = __shfl_sync(0xffffffffu, pb[kc][3], src2);
                pa[kc][0] = odd ? s01 : s00;
                pa[kc][1] = odd ? s11 : s10;
                pa[kc][2] = odd ? s21 : s20;
                pa[kc][3] = odd ? s31 : s30;
            }

            // ---- O += P V via ldmatrix B-frags from Vt ----
            #pragma unroll
            for (int g = 0; g < 4; g++) {
                #pragma unroll
                for (int np = 0; np < 4; np++) {
                    uint32_t vf[4];
                    const int row = (2 * np + (sel >> 1)) * 8 + within;
                    const int cc  = 2 * g + (sel & 1);
                    ldsm4(vf, vst + row * 128 + ((cc ^ (row & 7)) << 4));
                    mma_tf32(Oacc[2 * np],     pa[g], &vf[0]);
                    mma_tf32(Oacc[2 * np + 1], pa[g], &vf[2]);
                }
            }
        }
    }

    // ---- write normalized output (tf32 bits) to [B,L,D] ----
    const float inv0 = 1.0f / lrow0;
    const float inv1 = 1.0f / lrow1;
    float* o0 = att + ((size_t)(b * Lc + qrow0))     * Dd + h * DK;
    float* o1 = att + ((size_t)(b * Lc + qrow0 + 8)) * Dd + h * DK;
    #pragma unroll
    for (int nd = 0; nd < 8; nd++) {
        const int cc = nd * 8 + 2 * t4;
        float2 v0, v1;
        v0.x = __uint_as_float(f2tf32(Oacc[nd][0] * inv0));
        v0.y = __uint_as_float(f2tf32(Oacc[nd][1] * inv0));
        v1.x = __uint_as_float(f2tf32(Oacc[nd][2] * inv1));
        v1.y = __uint_as_float(f2tf32(Oacc[nd][3] * inv1));
        *(float2*)(o0 + cc) = v0;
        *(float2*)(o1 + cc) = v1;
    }
}

// ---------------- launch ----------------
extern "C" void kernel_launch(void* const* d_in, const int* in_sizes, int n_in,
                              void* d_out, int out_size)
{
    const float* q    = (const float*)d_in[0];
    const float* k    = (const float*)d_in[1];
    const float* v    = (const float*)d_in[2];
    const float* wq_w = (const float*)d_in[3];
    const float* wq_b = (const float*)d_in[4];
    const float* wk_w = (const float*)d_in[5];
    const float* wk_b = (const float*)d_in[6];
    const float* wv_w = (const float*)d_in[7];
    const float* wv_b = (const float*)d_in[8];
    const float* wo_w = (const float*)d_in[9];
    const float* wo_b = (const float*)d_in[10];
    float* out = (float*)d_out;

    float *pQ, *pK, *pV, *pVt, *pAtt, *pConv;
    cudaGetSymbolAddress((void**)&pQ,    g_Q);
    cudaGetSymbolAddress((void**)&pK,    g_K);
    cudaGetSymbolAddress((void**)&pV,    g_V);
    cudaGetSymbolAddress((void**)&pVt,   g_Vt);
    cudaGetSymbolAddress((void**)&pAtt,  g_att);
    cudaGetSymbolAddress((void**)&pConv, g_conv);

    cudaFuncSetAttribute(gemm_qkv_kernel, cudaFuncAttributeMaxDynamicSharedMemorySize, GEMM_SMEM_BYTES);
    cudaFuncSetAttribute(gemm_o_kernel,   cudaFuncAttributeMaxDynamicSharedMemorySize, GEMM_SMEM_BYTES);
    cudaFuncSetAttribute(attn_mma_kernel, cudaFuncAttributeMaxDynamicSharedMemorySize, ATTN_SMEM_BYTES);

    // ---- fused tf32 pre-convert ----
    ConvArgs ca;
    ca.s0 = (const float4*)q;    ca.s1 = (const float4*)k;    ca.s2 = (const float4*)v;
    ca.s3 = (const float4*)wq_w; ca.s4 = (const float4*)wk_w; ca.s5 = (const float4*)wv_w;
    ca.s6 = (const float4*)wo_w;
    ca.dst = (float4*)pConv;
    conv_all_kernel<<<SEG_TOT / 4 / 256, 256>>>(ca);

    const float* pqc = pConv + (size_t)SEG_Q  * 4;
    const float* pkc = pConv + (size_t)SEG_K  * 4;
    const float* pvc = pConv + (size_t)SEG_V  * 4;
    const float* pwq = pConv + (size_t)SEG_WQ * 4;
    const float* pwk = pConv + (size_t)SEG_WK * 4;
    const float* pwv = pConv + (size_t)SEG_WV * 4;
    const float* pwo = pConv + (size_t)SEG_WO * 4;

    QKVArgs args;
    args.X[0] = pqc;  args.X[1] = pkc;  args.X[2] = pvc;
    args.W[0] = pwq;  args.W[1] = pwk;  args.W[2] = pwv;
    args.bias[0] = wq_b; args.bias[1] = wk_b; args.bias[2] = wv_b;
    args.out[0] = pQ; args.out[1] = pK; args.out[2] = pV;

    dim3 gq(Dd / 128, Mtok / 256, 3);   // (8, 32, 3)
    gemm_qkv_kernel<<<gq, 256, GEMM_SMEM_BYTES>>>(args);

    dim3 gt(Lc / 32, DK / 32, Bc * Hh); // (64, 2, 64)
    vtrans_kernel<<<gt, 256>>>(pV, pVt);

    dim3 ga(Lc / 128, Hh, Bc);          // (16, 16, 4)
    attn_mma_kernel<<<ga, 256, ATTN_SMEM_BYTES>>>(pQ, pK, pVt, pAtt);

    dim3 gg(Dd / 128, Mtok / 256);      // (8, 32)
    gemm_o_kernel<<<gg, 256, GEMM_SMEM_BYTES>>>(pAtt, pwo, wo_b, out);
}

// round 11
// speedup vs baseline: 5.7080x; 1.0373x over previous
#include <cuda_runtime.h>
#include <cuda_bf16.h>
#include <math.h>
#include <cstdint>

constexpr int Bc = 4;
constexpr int Lc = 2048;
constexpr int Dd = 1024;
constexpr int Hh = 16;
constexpr int DK = 64;
constexpr int Mtok = Bc * Lc;   // 8192

// ---------------- scratch ----------------
__device__ float g_Q[Bc * Hh * Lc * DK];   // [B,H,L,DK] (tf32 bits)
__device__ float g_K[Bc * Hh * Lc * DK];
__device__ float g_Vt[Bc * Hh * DK * Lc];  // [B,H,DK,L] (tf32 bits)
__device__ float g_att[Bc * Lc * Dd];      // [B,L,D]    (tf32 bits)
__device__ float g_conv[7340032 * 4];      // concatenated tf32 copies

// segment offsets in float4 units
constexpr int SEG_Q  = 0;
constexpr int SEG_K  = 2097152;
constexpr int SEG_V  = 4194304;
constexpr int SEG_WQ = 6291456;
constexpr int SEG_WK = 6553600;
constexpr int SEG_WV = 6815744;
constexpr int SEG_WO = 7077888;
constexpr int SEG_TOT = 7340032;

// ---------------- helpers ----------------
__device__ __forceinline__ uint32_t f2tf32(float f) {
    uint32_t r;
    asm("cvt.rna.tf32.f32 %0, %1;" : "=r"(r) : "f"(f));
    return r;
}

__device__ __forceinline__ void mma_tf32(float* d, const uint32_t* a, const uint32_t* b) {
    asm volatile(
        "mma.sync.aligned.m16n8k8.row.col.f32.tf32.tf32.f32 "
        "{%0,%1,%2,%3}, {%4,%5,%6,%7}, {%8,%9}, {%0,%1,%2,%3};\n"
        : "+f"(d[0]), "+f"(d[1]), "+f"(d[2]), "+f"(d[3])
        : "r"(a[0]), "r"(a[1]), "r"(a[2]), "r"(a[3]), "r"(b[0]), "r"(b[1]));
}

__device__ __forceinline__ void ldsm4(uint32_t* r, uint32_t addr) {
    asm volatile("ldmatrix.sync.aligned.m8n8.x4.shared.b16 {%0,%1,%2,%3}, [%4];"
                 : "=r"(r[0]), "=r"(r[1]), "=r"(r[2]), "=r"(r[3]) : "r"(addr));
}

__device__ __forceinline__ uint32_t smem_u32(const void* p) {
    uint32_t a;
    asm("{ .reg .u64 t; cvta.to.shared.u64 t, %1; cvt.u32.u64 %0, t; }" : "=r"(a) : "l"(p));
    return a;
}

#define CP16(dst, src) \
    asm volatile("cp.async.cg.shared.global [%0], [%1], 16;" :: "r"(dst), "l"(src))
#define CP_COMMIT() asm volatile("cp.async.commit_group;")
#define CP_WAIT1()  asm volatile("cp.async.wait_group 1;")

// ---------------- fused tf32 pre-convert (all 7 tensors) ----------------
struct ConvArgs {
    const float4* s0; const float4* s1; const float4* s2;
    const float4* s3; const float4* s4; const float4* s5; const float4* s6;
    float4* dst;
};

__global__ void __launch_bounds__(256) conv_all_kernel(ConvArgs a)
{
    const int g = blockIdx.x * 256 + threadIdx.x;
    constexpr int NT = SEG_TOT / 4;
    #pragma unroll
    for (int p = 0; p < 4; p++) {
        const int idx = g + p * NT;
        float4 v;
        if (idx < SEG_WQ) {
            const int seg = idx >> 21;
            const int off = idx & 2097151;
            v = (seg == 0) ? a.s0[off] : (seg == 1) ? a.s1[off] : a.s2[off];
        } else {
            const int r = idx - SEG_WQ;
            const int seg = r >> 18;
            const int off = r & 262143;
            v = (seg == 0) ? a.s3[off] : (seg == 1) ? a.s4[off]
              : (seg == 2) ? a.s5[off] : a.s6[off];
        }
        uint4 u;
        u.x = f2tf32(v.x); u.y = f2tf32(v.y); u.z = f2tf32(v.z); u.w = f2tf32(v.w);
        ((uint4*)a.dst)[idx] = u;
    }
}

// =====================================================================
// GEMM: cp.async 3-stage pipeline + ldmatrix, tf32-bit inputs.
// CTA 256x128, 8 warps (4m x 2n), warp 64x64, BK=32.
// mode 0: fp32 out[m*1024+n]
// mode 1: tf32 bits out in [B,H,L,DK]
// mode 2: tf32 bits out in [B,H,DK,L]  (direct V transpose)
// =====================================================================
constexpr int AW = 256 * 32;
constexpr int BW = 128 * 32;
constexpr int STAGE_W = AW + BW;
constexpr int GEMM_SMEM_BYTES = 3 * STAGE_W * 4;  // 147456

__device__ __forceinline__ void gemm_core(const float* __restrict__ X,
                                          const float* __restrict__ W,
                                          const float* __restrict__ bias,
                                          float* __restrict__ out,
                                          int mode, int bx, int by,
                                          uint32_t sbase)
{
    const int tid  = threadIdx.x;
    const int w    = tid >> 5;
    const int lane = tid & 31;
    const int gid  = lane >> 2;
    const int t4   = lane & 3;

    const int m0 = by * 256;
    const int n0 = bx * 128;
    const int wm = (w >> 1) * 64;
    const int wn = (w & 1) * 64;

    const int lr = tid >> 3;
    const int ch = tid & 7;

    const int within = lane & 7;
    const int sel    = lane >> 3;

    float acc[4][8][4] = {};

    auto issue = [&](int stage, int kt) {
        const uint32_t ab = sbase + stage * (STAGE_W * 4);
        const uint32_t bb = ab + AW * 4;
        const float* ap = X + (size_t)(m0 + lr) * Dd + kt * 32 + ch * 4;
        #pragma unroll
        for (int i = 0; i < 8; i++) {
            const int row = lr + 32 * i;
            const uint32_t dst = ab + row * 128 + ((ch ^ (row & 7)) << 4);
            CP16(dst, ap + (size_t)(32 * i) * Dd);
        }
        const float* bp = W + (size_t)(n0 + lr) * Dd + kt * 32 + ch * 4;
        #pragma unroll
        for (int i = 0; i < 4; i++) {
            const int row = lr + 32 * i;
            const uint32_t dst = bb + row * 128 + ((ch ^ (row & 7)) << 4);
            CP16(dst, bp + (size_t)(32 * i) * Dd);
        }
        CP_COMMIT();
    };

    issue(0, 0);
    issue(1, 1);

    for (int kt = 0; kt < 32; kt++) {
        const int cs = kt % 3;
        CP_WAIT1();
        __syncthreads();
        if (kt < 30) issue((kt + 2) % 3, kt + 2);
        else         CP_COMMIT();

        const uint32_t ab = sbase + cs * (STAGE_W * 4);
        const uint32_t bb = ab + AW * 4;

        #pragma unroll
        for (int g = 0; g < 4; g++) {
            uint32_t af[4][4];
            #pragma unroll
            for (int tm = 0; tm < 4; tm++) {
                const int row = wm + tm * 16 + ((sel & 1) << 3) + within;
                const int cc  = 2 * g + (sel >> 1);
                ldsm4(af[tm], ab + row * 128 + ((cc ^ (row & 7)) << 4));
            }
            uint32_t bf[4][4];
            #pragma unroll
            for (int np = 0; np < 4; np++) {
                const int row = wn + (2 * np + (sel >> 1)) * 8 + within;
                const int cc  = 2 * g + (sel & 1);
                ldsm4(bf[np], bb + row * 128 + ((cc ^ (row & 7)) << 4));
            }
            #pragma unroll
            for (int tm = 0; tm < 4; tm++)
                #pragma unroll
                for (int np = 0; np < 4; np++) {
                    mma_tf32(acc[tm][2 * np],     af[tm], &bf[np][0]);
                    mma_tf32(acc[tm][2 * np + 1], af[tm], &bf[np][2]);
                }
        }
    }

    #pragma unroll
    for (int tm = 0; tm < 4; tm++) {
        const int r0 = m0 + wm + tm * 16 + gid;
        const int r1 = r0 + 8;
        #pragma unroll
        for (int tn = 0; tn < 8; tn++) {
            const int cc = n0 + wn + tn * 8 + t4 * 2;
            const float bv0 = __ldg(bias + cc);
            const float bv1 = __ldg(bias + cc + 1);
            float2 v0, v1;
            v0.x = acc[tm][tn][0] + bv0;  v0.y = acc[tm][tn][1] + bv1;
            v1.x = acc[tm][tn][2] + bv0;  v1.y = acc[tm][tn][3] + bv1;
            if (mode == 0) {
                *(float2*)(out + (size_t)r0 * Dd + cc) = v0;
                *(float2*)(out + (size_t)r1 * Dd + cc) = v1;
            } else if (mode == 1) {
                v0.x = __uint_as_float(f2tf32(v0.x));
                v0.y = __uint_as_float(f2tf32(v0.y));
                v1.x = __uint_as_float(f2tf32(v1.x));
                v1.y = __uint_as_float(f2tf32(v1.y));
                const int h = cc >> 6, dk = cc & 63;
                {
                    const int b = r0 >> 11, l = r0 & 2047;
                    *(float2*)(out + (((size_t)(b * Hh + h) * Lc + l) << 6) + dk) = v0;
                }
                {
                    const int b = r1 >> 11, l = r1 & 2047;
                    *(float2*)(out + (((size_t)(b * Hh + h) * Lc + l) << 6) + dk) = v1;
                }
            } else {   // mode 2: V -> [B,H,DK,L]
                const int h = cc >> 6, dk = cc & 63;
                {
                    const int b = r0 >> 11, l = r0 & 2047;
                    float* vb = out + ((size_t)(b * Hh + h) * DK + dk) * Lc;
                    vb[l]      = __uint_as_float(f2tf32(v0.x));
                    vb[Lc + l] = __uint_as_float(f2tf32(v0.y));
                }
                {
                    const int b = r1 >> 11, l = r1 & 2047;
                    float* vb = out + ((size_t)(b * Hh + h) * DK + dk) * Lc;
                    vb[l]      = __uint_as_float(f2tf32(v1.x));
                    vb[Lc + l] = __uint_as_float(f2tf32(v1.y));
                }
            }
        }
    }
}

struct QKVArgs {
    const float* X[3];
    const float* W[3];
    const float* bias[3];
    float* out[3];
};

__global__ void __launch_bounds__(256) gemm_qkv_kernel(QKVArgs args)
{
    extern __shared__ uint32_t sg[];
    const int z = blockIdx.z;
    gemm_core(args.X[z], args.W[z], args.bias[z], args.out[z],
              (z == 2) ? 2 : 1, blockIdx.x, blockIdx.y, smem_u32(sg));
}

__global__ void __launch_bounds__(256) gemm_o_kernel(const float* __restrict__ X,
                                                     const float* __restrict__ W,
                                                     const float* __restrict__ bias,
                                                     float* __restrict__ out)
{
    extern __shared__ uint32_t sg[];
    gemm_core(X, W, bias, out, 0, blockIdx.x, blockIdx.y, smem_u32(sg));
}

// =====================================================================
// Causal flash attention: 64-key tiles, cp.async 3-stage + ldmatrix.
// CTA: 128 q-rows, 8 warps; warp = 16 q x 64 keys.
// Stage: K 64x64 words (row=key, 256B rows) + Vt 64x64 words (row=d).
// =====================================================================
constexpr int ATT_KW = 64 * 64;
constexpr int ATT_VW = 64 * 64;
constexpr int ATT_STAGE_W = ATT_KW + ATT_VW;          // 8192 words
constexpr int ATTN_SMEM_BYTES = 3 * ATT_STAGE_W * 4;  // 98304

__global__ void __launch_bounds__(256, 2) attn_mma_kernel(const float* __restrict__ Qg,
                                                          const float* __restrict__ Kg,
                                                          const float* __restrict__ Vtg,
                                                          float* __restrict__ att)
{
    extern __shared__ uint32_t sa[];
    const uint32_t sb = smem_u32(sa);

    const int tid  = threadIdx.x;
    const int w    = tid >> 5;
    const int lane = tid & 31;
    const int gid  = lane >> 2;
    const int t4   = lane & 3;
    const int within = lane & 7;
    const int sel    = lane >> 3;

    const int qb = gridDim.x - 1 - blockIdx.x;   // LPT
    const int q0 = qb * 128;
    const int h  = blockIdx.y;
    const int b  = blockIdx.z;

    const int wq    = q0 + w * 16;
    const int qrow0 = wq + gid;

    const size_t base = (size_t)(b * Hh + h) * Lc * DK;
    const float* Qbh  = Qg + base;
    const float* Kbh  = Kg + base;
    const float* Vtbh = Vtg + base;   // [DK][L]

    // ---- Q fragments (tf32 bits; *0.125 exact) ----
    uint32_t qf[8][4];
    {
        const float* qp0 = Qbh + (size_t)qrow0 * DK;
        const float* qp1 = qp0 + 8 * DK;
        #pragma unroll
        for (int kc = 0; kc < 8; kc++) {
            const int c0 = kc * 8 + t4, c1 = c0 + 4;
            qf[kc][0] = __float_as_uint(__ldg(qp0 + c0) * 0.125f);
            qf[kc][1] = __float_as_uint(__ldg(qp1 + c0) * 0.125f);
            qf[kc][2] = __float_as_uint(__ldg(qp0 + c1) * 0.125f);
            qf[kc][3] = __float_as_uint(__ldg(qp1 + c1) * 0.125f);
        }
    }

    float Oacc[8][4] = {};
    float mrow0 = -3.0e38f, mrow1 = -3.0e38f;
    float lrow0 = 0.0f,     lrow1 = 0.0f;

    // ---- cp.async tile issue: K 1024 chunks + Vt 1024 chunks ----
    auto issueKV = [&](int stage, int k0) {
        const uint32_t kb = sb + stage * (ATT_STAGE_W * 4);
        const uint32_t vb = kb + ATT_KW * 4;
        #pragma unroll
        for (int i = 0; i < 4; i++) {
            const int idx = tid + i * 256;
            const int row = idx >> 4, c = idx & 15;
            CP16(kb + row * 256 + ((c ^ (row & 7)) << 4),
                 Kbh + (size_t)(k0 + row) * DK + c * 4);
            CP16(vb + row * 256 + ((c ^ (row & 7)) << 4),
                 Vtbh + (size_t)row * Lc + k0 + c * 4);
        }
        CP_COMMIT();
    };

    const int ntiles = q0 / 64 + 2;
    issueKV(0, 0);
    issueKV(1, 64);

    const int src0 = (lane & ~3) + (t4 >> 1);
    const int src2 = src0 + 2;
    const bool odd = (t4 & 1) != 0;

    for (int t = 0; t < ntiles; t++) {
        const int k0 = t * 64;
        const int cs = t % 3;
        CP_WAIT1();
        __syncthreads();
        if (t + 2 < ntiles) issueKV((t + 2) % 3, (t + 2) * 64);
        else                CP_COMMIT();

        if (k0 <= wq + 15) {
            const uint32_t kst = sb + cs * (ATT_STAGE_W * 4);
            const uint32_t vst = kst + ATT_KW * 4;

            // ---- S = Q' K^T (16q x 64k) ----
            float s[8][4] = {};
            #pragma unroll
            for (int st8 = 0; st8 < 8; st8++) {
                #pragma unroll
                for (int np = 0; np < 4; np++) {
                    uint32_t bf[4];
                    const int row = (2 * np + (sel >> 1)) * 8 + within;
                    const int cc  = 2 * st8 + (sel & 1);
                    ldsm4(bf, kst + row * 256 + ((cc ^ (row & 7)) << 4));
                    mma_tf32(s[2 * np],     qf[st8], &bf[0]);
                    mma_tf32(s[2 * np + 1], qf[st8], &bf[2]);
                }
            }
            // ---- causal mask (diagonal tiles only) ----
            if (k0 + 63 > wq) {
                #pragma unroll
                for (int tn = 0; tn < 8; tn++) {
                    const int c = k0 + tn * 8 + 2 * t4;
                    if (c     > qrow0)     s[tn][0] = -3.0e38f;
                    if (c + 1 > qrow0)     s[tn][1] = -3.0e38f;
                    if (c     > qrow0 + 8) s[tn][2] = -3.0e38f;
                    if (c + 1 > qrow0 + 8) s[tn][3] = -3.0e38f;
                }
            }
            // ---- register softmax ----
            float mx0 = s[0][0], mx1 = s[0][2];
            #pragma unroll
            for (int tn = 0; tn < 8; tn++) {
                mx0 = fmaxf(mx0, fmaxf(s[tn][0], s[tn][1]));
                mx1 = fmaxf(mx1, fmaxf(s[tn][2], s[tn][3]));
            }
            mx0 = fmaxf(mx0, __shfl_xor_sync(0xffffffffu, mx0, 1));
            mx0 = fmaxf(mx0, __shfl_xor_sync(0xffffffffu, mx0, 2));
            mx1 = fmaxf(mx1, __shfl_xor_sync(0xffffffffu, mx1, 1));
            mx1 = fmaxf(mx1, __shfl_xor_sync(0xffffffffu, mx1, 2));
            const float mn0 = fmaxf(mrow0, mx0);
            const float mn1 = fmaxf(mrow1, mx1);

            float ps0 = 0.0f, ps1 = 0.0f;
            #pragma unroll
            for (int tn = 0; tn < 8; tn++) {
                float p0 = __expf(s[tn][0] - mn0);
                float p1 = __expf(s[tn][1] - mn0);
                float p2 = __expf(s[tn][2] - mn1);
                float p3 = __expf(s[tn][3] - mn1);
                ps0 += p0 + p1;
                ps1 += p2 + p3;
                s[tn][0] = p0; s[tn][1] = p1; s[tn][2] = p2; s[tn][3] = p3;
            }
            ps0 += __shfl_xor_sync(0xffffffffu, ps0, 1);
            ps0 += __shfl_xor_sync(0xffffffffu, ps0, 2);
            ps1 += __shfl_xor_sync(0xffffffffu, ps1, 1);
            ps1 += __shfl_xor_sync(0xffffffffu, ps1, 2);

            const float al0 = __expf(mrow0 - mn0);
            const float al1 = __expf(mrow1 - mn1);
            lrow0 = lrow0 * al0 + ps0;
            lrow1 = lrow1 * al1 + ps1;
            mrow0 = mn0;
            mrow1 = mn1;
            #pragma unroll
            for (int nd = 0; nd < 8; nd++) {
                Oacc[nd][0] *= al0; Oacc[nd][1] *= al0;
                Oacc[nd][2] *= al1; Oacc[nd][3] *= al1;
            }

            // ---- per 8-key chunk: P shuffle->A-frag, then O += P V ----
            #pragma unroll
            for (int g = 0; g < 8; g++) {
                float f00 = __shfl_sync(0xffffffffu, s[g][0], src0);
                float f01 = __shfl_sync(0xffffffffu, s[g][1], src0);
                float f10 = __shfl_sync(0xffffffffu, s[g][2], src0);
                float f11 = __shfl_sync(0xffffffffu, s[g][3], src0);
                float f20 = __shfl_sync(0xffffffffu, s[g][0], src2);
                float f21 = __shfl_sync(0xffffffffu, s[g][1], src2);
                float f30 = __shfl_sync(0xffffffffu, s[g][2], src2);
                float f31 = __shfl_sync(0xffffffffu, s[g][3], src2);
                uint32_t pa[4];
                pa[0] = f2tf32(odd ? f01 : f00);
                pa[1] = f2tf32(odd ? f11 : f10);
                pa[2] = f2tf32(odd ? f21 : f20);
                pa[3] = f2tf32(odd ? f31 : f30);
                #pragma unroll
                for (int np = 0; np < 4; np++) {
                    uint32_t vf[4];
                    const int row = (2 * np + (sel >> 1)) * 8 + within;
                    const int cc  = 2 * g + (sel & 1);
                    ldsm4(vf, vst + row * 256 + ((cc ^ (row & 7)) << 4));
                    mma_tf32(Oacc[2 * np],     pa, &vf[0]);
                    mma_tf32(Oacc[2 * np + 1], pa, &vf[2]);
                }
            }
        }
    }

    // ---- write normalized output (tf32 bits) to [B,L,D] ----
    const float inv0 = 1.0f / lrow0;
    const float inv1 = 1.0f / lrow1;
    float* o0 = att + ((size_t)(b * Lc + qrow0))     * Dd + h * DK;
    float* o1 = att + ((size_t)(b * Lc + qrow0 + 8)) * Dd + h * DK;
    #pragma unroll
    for (int nd = 0; nd < 8; nd++) {
        const int cc = nd * 8 + 2 * t4;
        float2 v0, v1;
        v0.x = __uint_as_float(f2tf32(Oacc[nd][0] * inv0));
        v0.y = __uint_as_float(f2tf32(Oacc[nd][1] * inv0));
        v1.x = __uint_as_float(f2tf32(Oacc[nd][2] * inv1));
        v1.y = __uint_as_float(f2tf32(Oacc[nd][3] * inv1));
        *(float2*)(o0 + cc) = v0;
        *(float2*)(o1 + cc) = v1;
    }
}

// ---------------- launch ----------------
extern "C" void kernel_launch(void* const* d_in, const int* in_sizes, int n_in,
                              void* d_out, int out_size)
{
    const float* q    = (const float*)d_in[0];
    const float* k    = (const float*)d_in[1];
    const float* v    = (const float*)d_in[2];
    const float* wq_w = (const float*)d_in[3];
    const float* wq_b = (const float*)d_in[4];
    const float* wk_w = (const float*)d_in[5];
    const float* wk_b = (const float*)d_in[6];
    const float* wv_w = (const float*)d_in[7];
    const float* wv_b = (const float*)d_in[8];
    const float* wo_w = (const float*)d_in[9];
    const float* wo_b = (const float*)d_in[10];
    float* out = (float*)d_out;

    float *pQ, *pK, *pVt, *pAtt, *pConv;
    cudaGetSymbolAddress((void**)&pQ,    g_Q);
    cudaGetSymbolAddress((void**)&pK,    g_K);
    cudaGetSymbolAddress((void**)&pVt,   g_Vt);
    cudaGetSymbolAddress((void**)&pAtt,  g_att);
    cudaGetSymbolAddress((void**)&pConv, g_conv);

    cudaFuncSetAttribute(gemm_qkv_kernel, cudaFuncAttributeMaxDynamicSharedMemorySize, GEMM_SMEM_BYTES);
    cudaFuncSetAttribute(gemm_o_kernel,   cudaFuncAttributeMaxDynamicSharedMemorySize, GEMM_SMEM_BYTES);
    cudaFuncSetAttribute(attn_mma_kernel, cudaFuncAttributeMaxDynamicSharedMemorySize, ATTN_SMEM_BYTES);

    // ---- fused tf32 pre-convert ----
    ConvArgs ca;
    ca.s0 = (const float4*)q;    ca.s1 = (const float4*)k;    ca.s2 = (const float4*)v;
    ca.s3 = (const float4*)wq_w; ca.s4 = (const float4*)wk_w; ca.s5 = (const float4*)wv_w;
    ca.s6 = (const float4*)wo_w;
    ca.dst = (float4*)pConv;
    conv_all_kernel<<<SEG_TOT / 4 / 256, 256>>>(ca);

    const float* pqc = pConv + (size_t)SEG_Q  * 4;
    const float* pkc = pConv + (size_t)SEG_K  * 4;
    const float* pvc = pConv + (size_t)SEG_V  * 4;
    const float* pwq = pConv + (size_t)SEG_WQ * 4;
    const float* pwk = pConv + (size_t)SEG_WK * 4;
    const float* pwv = pConv + (size_t)SEG_WV * 4;
    const float* pwo = pConv + (size_t)SEG_WO * 4;

    QKVArgs args;
    args.X[0] = pqc;  args.X[1] = pkc;  args.X[2] = pvc;
    args.W[0] = pwq;  args.W[1] = pwk;  args.W[2] = pwv;
    args.bias[0] = wq_b; args.bias[1] = wk_b; args.bias[2] = wv_b;
    args.out[0] = pQ; args.out[1] = pK; args.out[2] = pVt;

    dim3 gq(Dd / 128, Mtok / 256, 3);   // (8, 32, 3)
    gemm_qkv_kernel<<<gq, 256, GEMM_SMEM_BYTES>>>(args);

    dim3 ga(Lc / 128, Hh, Bc);          // (16, 16, 4)
    attn_mma_kernel<<<ga, 256, ATTN_SMEM_BYTES>>>(pQ, pK, pVt, pAtt);

    dim3 gg(Dd / 128, Mtok / 256);      // (8, 32)
    gemm_o_kernel<<<gg, 256, GEMM_SMEM_BYTES>>>(pAtt, pwo, wo_b, out);
}